// round 7
// baseline (speedup 1.0000x reference)
#include <cuda_runtime.h>
#include <cuda_bf16.h>
#include <cstdint>

#define DEV __device__ __forceinline__

// B=32,S=32 -> N=1024 ; CTX=64 ; E=256 ; V=32000 ; D=512 ; MEM=4096
// L1: Cin=64 Lin=256 -> 32x127 | L2: 32x127 -> 64x62 | L3: 64x62 -> 128x30
// L4: 128x30 -> 256x14 (HALF lane packing) | L5: GEMM [1024,3584]x[512,3584]^T
// FC: [1024,1280] x [1280,32000] via mma.sync bf16 hi/lo split (3-term),
//     512-thread CTA (16 warps 4Mx4N, warp tile 32x32) for latency hiding.

__device__ float g_h1[1024 * 32 * 127];
__device__ float g_h2[1024 * 64 * 62];
__device__ float g_h3[1024 * 128 * 30];
__device__ float g_h4[1024 * 256 * 14];
__device__ float g_h4n[1024 * 3584];
__device__ float g_cfeat[1024 * 512];
__device__ float g_s[1024 * 1280];        // [ e(256) | cfeat_n(512) | m_out(512) ]
__device__ float g_scores[1024 * 4096];
__device__ float g_sum[5 * 512];
__device__ float g_ssq[5 * 512];
__device__ float g_affa[5 * 512];
__device__ float g_affb[5 * 512];
__device__ __nv_bfloat16 g_Bh[32000 * 1280];
__device__ __nv_bfloat16 g_Bl[32000 * 1280];
__device__ __nv_bfloat16 g_Ah[1024 * 1280];
__device__ __nv_bfloat16 g_Al[1024 * 1280];

DEV float leakyf(float v) { return v > 0.f ? v : 0.1f * v; }

// fast exp on the fma pipe: exp(x) = 2^(x*log2e), magic-round + deg-5 poly
DEV float fast_exp(float x) {
    x = fmaxf(x, -80.f);
    float t = x * 1.4426950408889634f;
    float fm = t + 12582912.f;                  // round-to-nearest int in low bits
    int ki = __float_as_int(fm);
    float f = t - (fm - 12582912.f);            // frac in [-0.5, 0.5]
    float p = 1.3333558146e-3f;
    p = fmaf(p, f, 9.6181291076e-3f);
    p = fmaf(p, f, 5.5504108664e-2f);
    p = fmaf(p, f, 2.4022650695e-1f);
    p = fmaf(p, f, 6.9314718056e-1f);
    p = fmaf(p, f, 1.0f);
    return p * __int_as_float((ki + (127 - 0x4B400000)) << 23);
}

__global__ void init_kernel() {
    int i = blockIdx.x * 256 + threadIdx.x;
    if (i < 5 * 512) { g_sum[i] = 0.f; g_ssq[i] = 0.f; }
    if (i < 1024 * 512) g_cfeat[i] = 0.f;
}

// ---------------- conv + leaky + stats -----------------------------
// HALF: lanes 0-15 handle channels [co0, co0+CO_T), lanes 16-31 handle
// [co0+CO_T, co0+2*CO_T) at the same output positions.
template <int CIN, int LIN, int COUT, int LOUT, int G, int CO_T, bool GATHER, bool HALF>
__global__ void __launch_bounds__(256) conv_kernel(
    const float* __restrict__ in, const int* __restrict__ cidx,
    const float* __restrict__ emb,
    const float* __restrict__ w, const float* __restrict__ bias,
    const float* __restrict__ aa, const float* __restrict__ ab,
    float* __restrict__ out, float* __restrict__ ssum, float* __restrict__ ssq)
{
    constexpr int KS = 8, PAD = 2;
    constexpr int SW = ((LIN + 2 * PAD + 1) / 2) * 2;
    extern __shared__ __align__(16) float in_s[];       // [CIN][SW]

    const int n = blockIdx.x;
    const int tid = threadIdx.x, warp = tid >> 5, lane = tid & 31;
    const int lpos = HALF ? (lane & 15) : lane;
    const int lhalf = HALF ? (lane >> 4) : 0;

    for (int i = tid; i < CIN * SW; i += 256) in_s[i] = 0.f;
    __syncthreads();

    if (GATHER) {
        for (int r = warp; r < CIN; r += 8) {
            int tok = cidx[n * CIN + r];
            const float4* src = (const float4*)(emb + (size_t)tok * 256);
            float* dst = &in_s[r * SW + PAD];
            #pragma unroll
            for (int i = 0; i < 2; i++) {
                float4 v = src[lane + 32 * i];
                int cb = (lane + 32 * i) * 4;
                dst[cb] = v.x; dst[cb + 1] = v.y; dst[cb + 2] = v.z; dst[cb + 3] = v.w;
            }
        }
    } else {
        for (int j = tid; j < CIN * LIN; j += 256) {
            int cin = j / LIN, l = j - cin * LIN;
            in_s[cin * SW + PAD + l] = aa[cin] * in[(size_t)n * CIN * LIN + j] + ab[cin];
        }
    }
    __syncthreads();

    int lo[G]; bool act[G];
    #pragma unroll
    for (int g = 0; g < G; g++) {
        int l = lpos + 32 * g;
        act[g] = (l < LOUT);
        lo[g] = act[g] ? l : (LOUT - 1);
    }

    constexpr int CPW = HALF ? (2 * CO_T) : CO_T;
    constexpr int OI = COUT / (8 * CPW);
    #pragma unroll 1
    for (int oi = 0; oi < OI; oi++) {
        const int co0 = (oi * 8 + warp) * CPW + lhalf * CO_T;
        float acc[CO_T][G];
        #pragma unroll
        for (int ct = 0; ct < CO_T; ct++) {
            float bv = bias[co0 + ct];
            #pragma unroll
            for (int g = 0; g < G; g++) acc[ct][g] = bv;
        }
        for (int cin = 0; cin < CIN; cin++) {
            const float* row = &in_s[cin * SW];
            float inv[G][KS];
            #pragma unroll
            for (int g = 0; g < G; g++) {
                int base = lo[g] * 2;
                #pragma unroll
                for (int kk = 0; kk < KS / 2; kk++) {
                    float2 p = *(const float2*)&row[base + 2 * kk];
                    inv[g][2 * kk] = p.x; inv[g][2 * kk + 1] = p.y;
                }
            }
            #pragma unroll
            for (int ct = 0; ct < CO_T; ct++) {
                const float4* wp = (const float4*)&w[((size_t)(co0 + ct) * CIN + cin) * KS];
                float4 w0 = __ldg(wp), w1 = __ldg(wp + 1);
                #pragma unroll
                for (int g = 0; g < G; g++) {
                    float a = acc[ct][g];
                    a = fmaf(w0.x, inv[g][0], a); a = fmaf(w0.y, inv[g][1], a);
                    a = fmaf(w0.z, inv[g][2], a); a = fmaf(w0.w, inv[g][3], a);
                    a = fmaf(w1.x, inv[g][4], a); a = fmaf(w1.y, inv[g][5], a);
                    a = fmaf(w1.z, inv[g][6], a); a = fmaf(w1.w, inv[g][7], a);
                    acc[ct][g] = a;
                }
            }
        }
        #pragma unroll
        for (int ct = 0; ct < CO_T; ct++) {
            const int co = co0 + ct;
            float s = 0.f, s2 = 0.f;
            #pragma unroll
            for (int g = 0; g < G; g++) {
                if (act[g]) {
                    float y = leakyf(acc[ct][g]);
                    out[((size_t)n * COUT + co) * LOUT + lo[g]] = y;
                    s += y; s2 += y * y;
                }
            }
            #pragma unroll
            for (int o = (HALF ? 8 : 16); o; o >>= 1) {
                s  += __shfl_xor_sync(~0u, s,  o);
                s2 += __shfl_xor_sync(~0u, s2, o);
            }
            if (lpos == 0) { atomicAdd(&ssum[co], s); atomicAdd(&ssq[co], s2); }
        }
    }
}

__global__ void bn_finalize_kernel(const float* __restrict__ ssum, const float* __restrict__ ssq,
                                   const float* __restrict__ gam, const float* __restrict__ bet,
                                   float* __restrict__ a, float* __restrict__ b,
                                   int cout, float invcnt)
{
    int c = threadIdx.x;
    if (c < cout) {
        float mu = ssum[c] * invcnt;
        float var = ssq[c] * invcnt - mu * mu;
        float av = gam[c] * rsqrtf(var + 1e-5f);
        a[c] = av;
        b[c] = bet[c] - mu * av;
    }
}

__global__ void affine4_kernel(const float* __restrict__ a, const float* __restrict__ b) {
    unsigned i = blockIdx.x * 256 + threadIdx.x;
    if (i < 1024u * 3584u) {
        unsigned cin = (i / 14u) & 255u;
        g_h4n[i] = a[cin] * g_h4[i] + b[cin];
    }
}

__global__ void colstats_kernel(const float* __restrict__ b5,
                                float* __restrict__ ssum, float* __restrict__ ssq) {
    int c = threadIdx.x;                  // 512 threads, 8 blocks x 128 rows
    int r0 = blockIdx.x * 128;
    float s = 0.f, s2 = 0.f;
    for (int r = 0; r < 128; r++) {
        float v = leakyf(g_cfeat[(size_t)(r0 + r) * 512 + c] + b5[c]);
        s += v; s2 += v * v;
    }
    atomicAdd(&ssum[c], s); atomicAdd(&ssq[c], s2);
}

__global__ void build_s_kernel(const int* __restrict__ x, const float* __restrict__ emb,
                               const float* __restrict__ b5,
                               const float* __restrict__ a5, const float* __restrict__ bb5) {
    int n = blockIdx.x, t = threadIdx.x;
    int tok = x[n];
    g_s[(size_t)n * 1280 + t] = emb[(size_t)tok * 256 + t];
    for (int j = t; j < 512; j += 256) {
        float y = leakyf(g_cfeat[(size_t)n * 512 + j] + b5[j]);
        g_s[(size_t)n * 1280 + 256 + j] = a5[j] * y + bb5[j];
        g_s[(size_t)n * 1280 + 768 + j] = 0.f;
    }
}

// ---------------- FFMA2 helpers (SIMT GEMM) -------------------------
DEV unsigned long long pk2(float x, float y) {
    unsigned long long r;
    asm("mov.b64 %0, {%1, %2};" : "=l"(r) : "r"(__float_as_uint(x)), "r"(__float_as_uint(y)));
    return r;
}
DEV void fma2(unsigned long long& d, unsigned long long a, unsigned long long b) {
    asm("fma.rn.f32x2 %0, %1, %2, %0;" : "+l"(d) : "l"(a), "l"(b));
}
DEV float2 unpk(unsigned long long v) {
    return make_float2(__uint_as_float((unsigned)v), __uint_as_float((unsigned)(v >> 32)));
}

// ---------------- 128x128x8 fp32 SIMT GEMM --------------------------
template <bool TB, bool BIAS, int EPI, int SPLIT>
__global__ void __launch_bounds__(256) gemm_kernel(
    int K, const float* __restrict__ A, int lda,
    const float* __restrict__ B, int ldb,
    const float* __restrict__ bias,
    float* __restrict__ C, int ldc, float scale)
{
    __shared__ __align__(16) float As[8][128];
    __shared__ __align__(16) float Bs[8][128];
    const int tid = threadIdx.x;
    const int tx = tid & 15, ty = tid >> 4;
    const int bn = blockIdx.x, bm = blockIdx.y;

    const int kb = K / SPLIT;
    const int k0 = blockIdx.z * kb;

    const int aRow = tid >> 1, aCol = (tid & 1) * 4;
    const int bRow = tid >> 5, bCol = (tid & 31) * 4;

    const float* Ap = A + (size_t)(bm * 128 + aRow) * lda + k0 + aCol;
    const float* Bp = TB ? (B + (size_t)(bn * 128 + aRow) * ldb + k0 + aCol)
                         : (B + (size_t)(k0 + bRow) * ldb + bn * 128 + bCol);

    unsigned long long acc[8][4];
    #pragma unroll
    for (int i = 0; i < 8; i++)
        #pragma unroll
        for (int j = 0; j < 4; j++) acc[i][j] = 0ull;

    const int T = kb / 8;
    float4 av = *(const float4*)Ap;
    float4 bv = *(const float4*)Bp;

    for (int kt = 0; kt < T; kt++) {
        As[aCol + 0][aRow] = av.x; As[aCol + 1][aRow] = av.y;
        As[aCol + 2][aRow] = av.z; As[aCol + 3][aRow] = av.w;
        if (TB) {
            Bs[aCol + 0][aRow] = bv.x; Bs[aCol + 1][aRow] = bv.y;
            Bs[aCol + 2][aRow] = bv.z; Bs[aCol + 3][aRow] = bv.w;
        } else {
            *(float4*)&Bs[bRow][bCol] = bv;
        }
        __syncthreads();
        if (kt + 1 < T) {
            av = *(const float4*)(Ap + (size_t)(kt + 1) * 8);
            bv = TB ? *(const float4*)(Bp + (size_t)(kt + 1) * 8)
                    : *(const float4*)(Bp + (size_t)(kt + 1) * 8 * ldb);
        }
        #pragma unroll
        for (int k = 0; k < 8; k++) {
            const float4 a0 = *(const float4*)&As[k][ty * 8];
            const float4 a1 = *(const float4*)&As[k][ty * 8 + 4];
            const float4 b0 = *(const float4*)&Bs[k][tx * 8];
            const float4 b1 = *(const float4*)&Bs[k][tx * 8 + 4];
            unsigned long long bp[4] = { pk2(b0.x, b0.y), pk2(b0.z, b0.w),
                                         pk2(b1.x, b1.y), pk2(b1.z, b1.w) };
            float am[8] = { a0.x, a0.y, a0.z, a0.w, a1.x, a1.y, a1.z, a1.w };
            #pragma unroll
            for (int i = 0; i < 8; i++) {
                unsigned long long ap = pk2(am[i], am[i]);
                #pragma unroll
                for (int j = 0; j < 4; j++) fma2(acc[i][j], ap, bp[j]);
            }
        }
        __syncthreads();
    }

    const int row0 = bm * 128 + ty * 8;
    const int col0 = bn * 128 + tx * 8;
    float bvals[8];
    if (BIAS) {
        #pragma unroll
        for (int j = 0; j < 8; j++) bvals[j] = bias[col0 + j];
    }
    #pragma unroll
    for (int i = 0; i < 8; i++) {
        float f[8];
        #pragma unroll
        for (int j = 0; j < 4; j++) {
            float2 u = unpk(acc[i][j]);
            f[2 * j] = u.x; f[2 * j + 1] = u.y;
        }
        if (SPLIT > 1) {
            #pragma unroll
            for (int j = 0; j < 8; j++)
                atomicAdd(&C[(size_t)(row0 + i) * ldc + col0 + j], f[j]);
        } else {
            #pragma unroll
            for (int j = 0; j < 8; j++) {
                if (BIAS) f[j] += bvals[j];
                if (EPI == 1) f[j] = leakyf(f[j]);
                if (EPI == 2) f[j] *= scale;
            }
            float* cp = &C[(size_t)(row0 + i) * ldc + col0];
            *(float4*)cp = make_float4(f[0], f[1], f[2], f[3]);
            *(float4*)(cp + 4) = make_float4(f[4], f[5], f[6], f[7]);
        }
    }
}

// ---------------- row softmax (poly exp on fma pipe) ----------------
__global__ void __launch_bounds__(256) softmax_kernel(float* __restrict__ buf, int W) {
    float* row = buf + (size_t)blockIdx.x * W;
    __shared__ float red[8];
    const int t = threadIdx.x, lane = t & 31, wp = t >> 5;

    float m = -3.402823e38f;
    for (int i = t; i < W; i += 256) m = fmaxf(m, row[i]);
    #pragma unroll
    for (int o = 16; o; o >>= 1) m = fmaxf(m, __shfl_xor_sync(~0u, m, o));
    if (lane == 0) red[wp] = m;
    __syncthreads();
    float mm = red[0];
    #pragma unroll
    for (int i = 1; i < 8; i++) mm = fmaxf(mm, red[i]);
    __syncthreads();

    float s = 0.f;
    for (int i = t; i < W; i += 256) { float e = fast_exp(row[i] - mm); row[i] = e; s += e; }
    #pragma unroll
    for (int o = 16; o; o >>= 1) s += __shfl_xor_sync(~0u, s, o);
    if (lane == 0) red[wp] = s;
    __syncthreads();
    float tot = red[0];
    #pragma unroll
    for (int i = 1; i < 8; i++) tot += red[i];
    float inv = 1.f / tot;
    for (int i = t; i < W; i += 256) row[i] *= inv;
}

// ======================= tensor-core FC path ========================

// transpose fcW [1280][32000] -> bf16 hi/lo planes [32000][1280]
__global__ void transW_kernel(const float* __restrict__ W,
                              __nv_bfloat16* __restrict__ Bh, __nv_bfloat16* __restrict__ Bl) {
    __shared__ float t[32][33];
    int n0 = blockIdx.x * 32, k0 = blockIdx.y * 32;
    for (int i = threadIdx.y; i < 32; i += 8)
        t[i][threadIdx.x] = W[(size_t)(k0 + i) * 32000 + n0 + threadIdx.x];
    __syncthreads();
    for (int i = threadIdx.y; i < 32; i += 8) {
        float v = t[threadIdx.x][i];
        size_t o = (size_t)(n0 + i) * 1280 + k0 + threadIdx.x;
        __nv_bfloat16 h = __float2bfloat16(v);
        Bh[o] = h;
        Bl[o] = __float2bfloat16(v - __bfloat162float(h));
    }
}

__global__ void splitA_kernel(const float* __restrict__ S,
                              __nv_bfloat16* __restrict__ Ah, __nv_bfloat16* __restrict__ Al) {
    int i = blockIdx.x * 256 + threadIdx.x;   // grid covers 1024*1280
    float v = S[i];
    __nv_bfloat16 h = __float2bfloat16(v);
    Ah[i] = h;
    Al[i] = __float2bfloat16(v - __bfloat162float(h));
}

DEV uint32_t smem_u32(const void* p) {
    uint32_t a;
    asm("{ .reg .u64 t; cvta.to.shared.u64 t, %1; cvt.u32.u64 %0, t; }" : "=r"(a) : "l"(p));
    return a;
}

DEV void ldsm4(uint32_t* r, uint32_t addr) {
    asm volatile("ldmatrix.sync.aligned.m8n8.x4.shared.b16 {%0,%1,%2,%3}, [%4];"
                 : "=r"(r[0]), "=r"(r[1]), "=r"(r[2]), "=r"(r[3]) : "r"(addr));
}
DEV void ldsm2(uint32_t* r, uint32_t addr) {
    asm volatile("ldmatrix.sync.aligned.m8n8.x2.shared.b16 {%0,%1}, [%2];"
                 : "=r"(r[0]), "=r"(r[1]) : "r"(addr));
}
DEV void mma16816(float* d, const uint32_t* a, const uint32_t* b) {
    asm volatile(
        "mma.sync.aligned.m16n8k16.row.col.f32.bf16.bf16.f32 "
        "{%0,%1,%2,%3}, {%4,%5,%6,%7}, {%8,%9}, {%0,%1,%2,%3};"
        : "+f"(d[0]), "+f"(d[1]), "+f"(d[2]), "+f"(d[3])
        : "r"(a[0]), "r"(a[1]), "r"(a[2]), "r"(a[3]), "r"(b[0]), "r"(b[1]));
}

// C[1024,32000] = Ahl @ Bhl^T + bias ; 128x128 tiles, 16 warps (4M x 4N),
// warp tile 32x32, BK=32, cp.async double buffer, smem row stride 80B.
__global__ void __launch_bounds__(512) fc_mma_kernel(
    const __nv_bfloat16* __restrict__ Ah, const __nv_bfloat16* __restrict__ Al,
    const __nv_bfloat16* __restrict__ Bh, const __nv_bfloat16* __restrict__ Bl,
    const float* __restrict__ bias, float* __restrict__ C)
{
    extern __shared__ __align__(16) char smem[];
    const int tid = threadIdx.x, lane = tid & 31, warp = tid >> 5;
    const int wm = warp & 3, wn = warp >> 2;
    const int row0 = blockIdx.x * 128, col0 = blockIdx.y * 128;

    const uint32_t sb = smem_u32(smem);
    constexpr uint32_t PLANE = 10240;        // 128 rows * 80 B
    constexpr uint32_t STAGE = 4 * PLANE;    // Ah | Al | Bh | Bl

    const __nv_bfloat16* src0 = Ah + (size_t)row0 * 1280;
    const __nv_bfloat16* src1 = Al + (size_t)row0 * 1280;
    const __nv_bfloat16* src2 = Bh + (size_t)col0 * 1280;
    const __nv_bfloat16* src3 = Bl + (size_t)col0 * 1280;

    const int lrow = tid >> 2, lseg = tid & 3;   // 512 threads: 128 rows x 4 segs

    auto load_stage = [&](int chunk, int buf) {
        const uint32_t dst0 = sb + (uint32_t)buf * STAGE;
        const int k0 = chunk * 32;
        const __nv_bfloat16* srcs[4] = { src0, src1, src2, src3 };
        #pragma unroll
        for (int p = 0; p < 4; p++) {
            uint32_t d = dst0 + (uint32_t)p * PLANE + lrow * 80 + lseg * 16;
            const void* s = srcs[p] + (size_t)lrow * 1280 + k0 + lseg * 8;
            asm volatile("cp.async.cg.shared.global [%0], [%1], 16;"
                         :: "r"(d), "l"(s) : "memory");
        }
        asm volatile("cp.async.commit_group;" ::: "memory");
    };

    float acc[2][4][4];
    #pragma unroll
    for (int mi = 0; mi < 2; mi++)
        #pragma unroll
        for (int ni = 0; ni < 4; ni++)
            #pragma unroll
            for (int j = 0; j < 4; j++) acc[mi][ni][j] = 0.f;

    load_stage(0, 0);

    constexpr int CH = 40;                   // 1280 / 32
    for (int c = 0; c < CH; c++) {
        if (c + 1 < CH) {
            load_stage(c + 1, (c + 1) & 1);
            asm volatile("cp.async.wait_group 1;" ::: "memory");
        } else {
            asm volatile("cp.async.wait_group 0;" ::: "memory");
        }
        __syncthreads();

        const uint32_t st = sb + (uint32_t)(c & 1) * STAGE;
        #pragma unroll
        for (int ks = 0; ks < 2; ks++) {
            uint32_t ah[2][4], al[2][4], bh[4][2], bl[4][2];
            #pragma unroll
            for (int mi = 0; mi < 2; mi++) {
                int row = wm * 32 + mi * 16 + (lane & 15);
                uint32_t off = (uint32_t)row * 80 + ks * 32 + (lane >> 4) * 16;
                ldsm4(ah[mi], st + off);
                ldsm4(al[mi], st + PLANE + off);
            }
            #pragma unroll
            for (int ni = 0; ni < 4; ni++) {
                int row = wn * 32 + ni * 8 + (lane & 7);
                uint32_t off = (uint32_t)row * 80 + ks * 32 + ((lane >> 3) & 1) * 16;
                ldsm2(bh[ni], st + 2 * PLANE + off);
                ldsm2(bl[ni], st + 3 * PLANE + off);
            }
            #pragma unroll
            for (int mi = 0; mi < 2; mi++)
                #pragma unroll
                for (int ni = 0; ni < 4; ni++) {
                    mma16816(acc[mi][ni], ah[mi], bh[ni]);
                    mma16816(acc[mi][ni], ah[mi], bl[ni]);
                    mma16816(acc[mi][ni], al[mi], bh[ni]);
                }
        }
        __syncthreads();
    }

    // epilogue: d0,d1 -> (r, cc..cc+1); d2,d3 -> (r+8, cc..cc+1)
    #pragma unroll
    for (int mi = 0; mi < 2; mi++) {
        int r = row0 + wm * 32 + mi * 16 + (lane >> 2);
        #pragma unroll
        for (int ni = 0; ni < 4; ni++) {
            int cc = col0 + wn * 32 + ni * 8 + (lane & 3) * 2;
            float b0 = bias[cc], b1 = bias[cc + 1];
            float* p0 = C + (size_t)r * 32000 + cc;
            float* p1 = p0 + (size_t)8 * 32000;
            *(float2*)p0 = make_float2(acc[mi][ni][0] + b0, acc[mi][ni][1] + b1);
            *(float2*)p1 = make_float2(acc[mi][ni][2] + b0, acc[mi][ni][3] + b1);
        }
    }
}

// ------------------------------------------------------------------
extern "C" void kernel_launch(void* const* d_in, const int* in_sizes, int n_in,
                              void* d_out, int out_size)
{
    (void)in_sizes; (void)n_in; (void)out_size;
    const int*   x    = (const int*)  d_in[0];
    const int*   c    = (const int*)  d_in[1];
    const float* emb  = (const float*)d_in[2];
    const float* w1 = (const float*)d_in[3],  *b1 = (const float*)d_in[4];
    const float* gm1= (const float*)d_in[5],  *be1= (const float*)d_in[6];
    const float* w2 = (const float*)d_in[7],  *b2 = (const float*)d_in[8];
    const float* gm2= (const float*)d_in[9],  *be2= (const float*)d_in[10];
    const float* w3 = (const float*)d_in[11], *b3 = (const float*)d_in[12];
    const float* gm3= (const float*)d_in[13], *be3= (const float*)d_in[14];
    const float* w4 = (const float*)d_in[15], *b4 = (const float*)d_in[16];
    const float* gm4= (const float*)d_in[17], *be4= (const float*)d_in[18];
    const float* w5 = (const float*)d_in[19], *b5 = (const float*)d_in[20];
    const float* gm5= (const float*)d_in[21], *be5= (const float*)d_in[22];
    const float* fcW = (const float*)d_in[23], *fcb = (const float*)d_in[24];
    const float* memK= (const float*)d_in[25], *memV= (const float*)d_in[26];
    float* out = (float*)d_out;

    float *h1, *h2, *h3, *h4, *h4n, *cf, *sbuf, *sc, *su, *sq, *fa, *fb;
    __nv_bfloat16 *gBh, *gBl, *gAh, *gAl;
    cudaGetSymbolAddress((void**)&h1, g_h1);
    cudaGetSymbolAddress((void**)&h2, g_h2);
    cudaGetSymbolAddress((void**)&h3, g_h3);
    cudaGetSymbolAddress((void**)&h4, g_h4);
    cudaGetSymbolAddress((void**)&h4n, g_h4n);
    cudaGetSymbolAddress((void**)&cf, g_cfeat);
    cudaGetSymbolAddress((void**)&sbuf, g_s);
    cudaGetSymbolAddress((void**)&sc, g_scores);
    cudaGetSymbolAddress((void**)&su, g_sum);
    cudaGetSymbolAddress((void**)&sq, g_ssq);
    cudaGetSymbolAddress((void**)&fa, g_affa);
    cudaGetSymbolAddress((void**)&fb, g_affb);
    cudaGetSymbolAddress((void**)&gBh, g_Bh);
    cudaGetSymbolAddress((void**)&gBl, g_Bl);
    cudaGetSymbolAddress((void**)&gAh, g_Ah);
    cudaGetSymbolAddress((void**)&gAl, g_Al);

    init_kernel<<<2048, 256>>>();

    // fcW -> bf16 hi/lo planes (depends only on fcW)
    transW_kernel<<<dim3(1000, 40), dim3(32, 8)>>>(fcW, gBh, gBl);

    // conv1: gather emb, CIN=64 LIN=256 -> 32x127. smem 66560 B
    auto k1 = conv_kernel<64, 256, 32, 127, 4, 4, true, false>;
    cudaFuncSetAttribute(k1, cudaFuncAttributeMaxDynamicSharedMemorySize, 66560);
    k1<<<1024, 256, 66560>>>(nullptr, c, emb, w1, b1, nullptr, nullptr,
                             h1, su + 0, sq + 0);
    bn_finalize_kernel<<<1, 512>>>(su + 0, sq + 0, gm1, be1, fa + 0, fb + 0,
                                   32, 1.f / (1024.f * 127.f));

    conv_kernel<32, 127, 64, 62, 2, 4, false, false><<<1024, 256, 32 * 132 * 4>>>(
        h1, nullptr, nullptr, w2, b2, fa + 0, fb + 0, h2, su + 512, sq + 512);
    bn_finalize_kernel<<<1, 512>>>(su + 512, sq + 512, gm2, be2, fa + 512, fb + 512,
                                   64, 1.f / (1024.f * 62.f));

    conv_kernel<64, 62, 128, 30, 1, 4, false, false><<<1024, 256, 64 * 66 * 4>>>(
        h2, nullptr, nullptr, w3, b3, fa + 512, fb + 512, h3, su + 1024, sq + 1024);
    bn_finalize_kernel<<<1, 512>>>(su + 1024, sq + 1024, gm3, be3, fa + 1024, fb + 1024,
                                   128, 1.f / (1024.f * 30.f));

    // conv4 with HALF lane packing: 28/32 active lanes instead of 14/32
    conv_kernel<128, 30, 256, 14, 1, 4, false, true><<<1024, 256, 128 * 34 * 4>>>(
        h3, nullptr, nullptr, w4, b4, fa + 1024, fb + 1024, h4, su + 1536, sq + 1536);
    bn_finalize_kernel<<<1, 512>>>(su + 1536, sq + 1536, gm4, be4, fa + 1536, fb + 1536,
                                   256, 1.f / (1024.f * 14.f));

    affine4_kernel<<<14336, 256>>>(fa + 1536, fb + 1536);

    // conv5 as GEMM: [1024,3584] x [512,3584]^T -> g_cfeat (split-K=4, atomic)
    gemm_kernel<true, false, 0, 4><<<dim3(4, 8, 4), 256>>>(
        3584, h4n, 3584, w5, 3584, nullptr, cf, 512, 0.f);

    colstats_kernel<<<8, 512>>>(b5, su + 2048, sq + 2048);
    bn_finalize_kernel<<<1, 512>>>(su + 2048, sq + 2048, gm5, be5, fa + 2048, fb + 2048,
                                   512, 1.f / 1024.f);
    build_s_kernel<<<1024, 256>>>(x, emb, b5, fa + 2048, fb + 2048);

    // scores = cfeat_n @ memK^T / sqrt(512)
    gemm_kernel<true, false, 2, 1><<<dim3(32, 8, 1), 256>>>(
        512, sbuf + 256, 1280, memK, 512, nullptr, sc, 4096, 0.04419417382f);
    softmax_kernel<<<1024, 256>>>(sc, 4096);

    // m_out = attn @ memV  (split-K=4, atomic into g_s[:,768:1280])
    gemm_kernel<false, false, 0, 4><<<dim3(4, 8, 4), 256>>>(
        4096, sc, 4096, memV, 512, nullptr, sbuf + 768, 1280, 0.f);

    // s -> bf16 hi/lo planes, then tensor-core FC
    splitA_kernel<<<5120, 256>>>(sbuf, gAh, gAl);
    cudaFuncSetAttribute(fc_mma_kernel, cudaFuncAttributeMaxDynamicSharedMemorySize, 81920);
    fc_mma_kernel<<<dim3(8, 250), 512, 81920>>>(gAh, gAl, gBh, gBl, fcb, out);

    softmax_kernel<<<1024, 256>>>(out, 32000);
}

// round 8
// speedup vs baseline: 1.1256x; 1.1256x over previous
#include <cuda_runtime.h>
#include <cuda_bf16.h>
#include <cuda_fp16.h>
#include <cstdint>

#define DEV __device__ __forceinline__

// B=32,S=32 -> N=1024 ; CTX=64 ; E=256 ; V=32000 ; D=512 ; MEM=4096
// L1: Cin=64 Lin=256 -> 32x127 | L2: 32x127 -> 64x62 | L3: 64x62 -> 128x30
// L4: 128x30 -> 256x14 (HALF lane packing) | L5: GEMM [1024,3584]x[512,3584]^T
// FC: [1024,1280] x [1280,32000] via mma.sync fp16: A 2-plane (exact),
//     B 1-plane -> 2 MMAs per fragment (error ~1.5e-4 << 1e-3 threshold).

__device__ float g_h1[1024 * 32 * 127];
__device__ float g_h2[1024 * 64 * 62];
__device__ float g_h3[1024 * 128 * 30];
__device__ float g_h4[1024 * 256 * 14];
__device__ float g_h4n[1024 * 3584];
__device__ float g_cfeat[1024 * 512];
__device__ float g_s[1024 * 1280];        // [ e(256) | cfeat_n(512) | m_out(512) ]
__device__ float g_scores[1024 * 4096];
__device__ float g_sum[5 * 512];
__device__ float g_ssq[5 * 512];
__device__ float g_affa[5 * 512];
__device__ float g_affb[5 * 512];
__device__ __half g_Bh[32000 * 1280];
__device__ __half g_Ah[1024 * 1280];
__device__ __half g_Al[1024 * 1280];

DEV float leakyf(float v) { return v > 0.f ? v : 0.1f * v; }

// fast exp on the fma pipe: exp(x) = 2^(x*log2e), magic-round + deg-5 poly
DEV float fast_exp(float x) {
    x = fmaxf(x, -80.f);
    float t = x * 1.4426950408889634f;
    float fm = t + 12582912.f;                  // round-to-nearest int in low bits
    int ki = __float_as_int(fm);
    float f = t - (fm - 12582912.f);            // frac in [-0.5, 0.5]
    float p = 1.3333558146e-3f;
    p = fmaf(p, f, 9.6181291076e-3f);
    p = fmaf(p, f, 5.5504108664e-2f);
    p = fmaf(p, f, 2.4022650695e-1f);
    p = fmaf(p, f, 6.9314718056e-1f);
    p = fmaf(p, f, 1.0f);
    return p * __int_as_float((ki + (127 - 0x4B400000)) << 23);
}

__global__ void init_kernel() {
    int i = blockIdx.x * 256 + threadIdx.x;
    if (i < 5 * 512) { g_sum[i] = 0.f; g_ssq[i] = 0.f; }
    if (i < 1024 * 512) g_cfeat[i] = 0.f;
}

// ---------------- conv + leaky + stats -----------------------------
// HALF: lanes 0-15 handle channels [co0, co0+CO_T), lanes 16-31 handle
// [co0+CO_T, co0+2*CO_T) at the same output positions.
template <int CIN, int LIN, int COUT, int LOUT, int G, int CO_T, bool GATHER, bool HALF>
__global__ void __launch_bounds__(256) conv_kernel(
    const float* __restrict__ in, const int* __restrict__ cidx,
    const float* __restrict__ emb,
    const float* __restrict__ w, const float* __restrict__ bias,
    const float* __restrict__ aa, const float* __restrict__ ab,
    float* __restrict__ out, float* __restrict__ ssum, float* __restrict__ ssq)
{
    constexpr int KS = 8, PAD = 2;
    constexpr int SW = ((LIN + 2 * PAD + 1) / 2) * 2;
    extern __shared__ __align__(16) float in_s[];       // [CIN][SW]

    const int n = blockIdx.x;
    const int tid = threadIdx.x, warp = tid >> 5, lane = tid & 31;
    const int lpos = HALF ? (lane & 15) : lane;
    const int lhalf = HALF ? (lane >> 4) : 0;

    for (int i = tid; i < CIN * SW; i += 256) in_s[i] = 0.f;
    __syncthreads();

    if (GATHER) {
        for (int r = warp; r < CIN; r += 8) {
            int tok = cidx[n * CIN + r];
            const float4* src = (const float4*)(emb + (size_t)tok * 256);
            float* dst = &in_s[r * SW + PAD];
            #pragma unroll
            for (int i = 0; i < 2; i++) {
                float4 v = src[lane + 32 * i];
                int cb = (lane + 32 * i) * 4;
                dst[cb] = v.x; dst[cb + 1] = v.y; dst[cb + 2] = v.z; dst[cb + 3] = v.w;
            }
        }
    } else {
        for (int j = tid; j < CIN * LIN; j += 256) {
            int cin = j / LIN, l = j - cin * LIN;
            in_s[cin * SW + PAD + l] = aa[cin] * in[(size_t)n * CIN * LIN + j] + ab[cin];
        }
    }
    __syncthreads();

    int lo[G]; bool act[G];
    #pragma unroll
    for (int g = 0; g < G; g++) {
        int l = lpos + 32 * g;
        act[g] = (l < LOUT);
        lo[g] = act[g] ? l : (LOUT - 1);
    }

    constexpr int CPW = HALF ? (2 * CO_T) : CO_T;
    constexpr int OI = COUT / (8 * CPW);
    #pragma unroll 1
    for (int oi = 0; oi < OI; oi++) {
        const int co0 = (oi * 8 + warp) * CPW + lhalf * CO_T;
        float acc[CO_T][G];
        #pragma unroll
        for (int ct = 0; ct < CO_T; ct++) {
            float bv = bias[co0 + ct];
            #pragma unroll
            for (int g = 0; g < G; g++) acc[ct][g] = bv;
        }
        for (int cin = 0; cin < CIN; cin++) {
            const float* row = &in_s[cin * SW];
            float inv[G][KS];
            #pragma unroll
            for (int g = 0; g < G; g++) {
                int base = lo[g] * 2;
                #pragma unroll
                for (int kk = 0; kk < KS / 2; kk++) {
                    float2 p = *(const float2*)&row[base + 2 * kk];
                    inv[g][2 * kk] = p.x; inv[g][2 * kk + 1] = p.y;
                }
            }
            #pragma unroll
            for (int ct = 0; ct < CO_T; ct++) {
                const float4* wp = (const float4*)&w[((size_t)(co0 + ct) * CIN + cin) * KS];
                float4 w0 = __ldg(wp), w1 = __ldg(wp + 1);
                #pragma unroll
                for (int g = 0; g < G; g++) {
                    float a = acc[ct][g];
                    a = fmaf(w0.x, inv[g][0], a); a = fmaf(w0.y, inv[g][1], a);
                    a = fmaf(w0.z, inv[g][2], a); a = fmaf(w0.w, inv[g][3], a);
                    a = fmaf(w1.x, inv[g][4], a); a = fmaf(w1.y, inv[g][5], a);
                    a = fmaf(w1.z, inv[g][6], a); a = fmaf(w1.w, inv[g][7], a);
                    acc[ct][g] = a;
                }
            }
        }
        #pragma unroll
        for (int ct = 0; ct < CO_T; ct++) {
            const int co = co0 + ct;
            float s = 0.f, s2 = 0.f;
            #pragma unroll
            for (int g = 0; g < G; g++) {
                if (act[g]) {
                    float y = leakyf(acc[ct][g]);
                    out[((size_t)n * COUT + co) * LOUT + lo[g]] = y;
                    s += y; s2 += y * y;
                }
            }
            #pragma unroll
            for (int o = (HALF ? 8 : 16); o; o >>= 1) {
                s  += __shfl_xor_sync(~0u, s,  o);
                s2 += __shfl_xor_sync(~0u, s2, o);
            }
            if (lpos == 0) { atomicAdd(&ssum[co], s); atomicAdd(&ssq[co], s2); }
        }
    }
}

__global__ void bn_finalize_kernel(const float* __restrict__ ssum, const float* __restrict__ ssq,
                                   const float* __restrict__ gam, const float* __restrict__ bet,
                                   float* __restrict__ a, float* __restrict__ b,
                                   int cout, float invcnt)
{
    int c = threadIdx.x;
    if (c < cout) {
        float mu = ssum[c] * invcnt;
        float var = ssq[c] * invcnt - mu * mu;
        float av = gam[c] * rsqrtf(var + 1e-5f);
        a[c] = av;
        b[c] = bet[c] - mu * av;
    }
}

__global__ void affine4_kernel(const float* __restrict__ a, const float* __restrict__ b) {
    unsigned i = blockIdx.x * 256 + threadIdx.x;
    if (i < 1024u * 3584u) {
        unsigned cin = (i / 14u) & 255u;
        g_h4n[i] = a[cin] * g_h4[i] + b[cin];
    }
}

__global__ void colstats_kernel(const float* __restrict__ b5,
                                float* __restrict__ ssum, float* __restrict__ ssq) {
    int c = threadIdx.x;                  // 512 threads, 8 blocks x 128 rows
    int r0 = blockIdx.x * 128;
    float s = 0.f, s2 = 0.f;
    for (int r = 0; r < 128; r++) {
        float v = leakyf(g_cfeat[(size_t)(r0 + r) * 512 + c] + b5[c]);
        s += v; s2 += v * v;
    }
    atomicAdd(&ssum[c], s); atomicAdd(&ssq[c], s2);
}

__global__ void build_s_kernel(const int* __restrict__ x, const float* __restrict__ emb,
                               const float* __restrict__ b5,
                               const float* __restrict__ a5, const float* __restrict__ bb5) {
    int n = blockIdx.x, t = threadIdx.x;
    int tok = x[n];
    g_s[(size_t)n * 1280 + t] = emb[(size_t)tok * 256 + t];
    for (int j = t; j < 512; j += 256) {
        float y = leakyf(g_cfeat[(size_t)n * 512 + j] + b5[j]);
        g_s[(size_t)n * 1280 + 256 + j] = a5[j] * y + bb5[j];
        g_s[(size_t)n * 1280 + 768 + j] = 0.f;
    }
}

// ---------------- FFMA2 helpers (SIMT GEMM) -------------------------
DEV unsigned long long pk2(float x, float y) {
    unsigned long long r;
    asm("mov.b64 %0, {%1, %2};" : "=l"(r) : "r"(__float_as_uint(x)), "r"(__float_as_uint(y)));
    return r;
}
DEV void fma2(unsigned long long& d, unsigned long long a, unsigned long long b) {
    asm("fma.rn.f32x2 %0, %1, %2, %0;" : "+l"(d) : "l"(a), "l"(b));
}
DEV float2 unpk(unsigned long long v) {
    return make_float2(__uint_as_float((unsigned)v), __uint_as_float((unsigned)(v >> 32)));
}

// ---------------- 128x128x8 fp32 SIMT GEMM --------------------------
template <bool TB, bool BIAS, int EPI, int SPLIT>
__global__ void __launch_bounds__(256) gemm_kernel(
    int K, const float* __restrict__ A, int lda,
    const float* __restrict__ B, int ldb,
    const float* __restrict__ bias,
    float* __restrict__ C, int ldc, float scale)
{
    __shared__ __align__(16) float As[8][128];
    __shared__ __align__(16) float Bs[8][128];
    const int tid = threadIdx.x;
    const int tx = tid & 15, ty = tid >> 4;
    const int bn = blockIdx.x, bm = blockIdx.y;

    const int kb = K / SPLIT;
    const int k0 = blockIdx.z * kb;

    const int aRow = tid >> 1, aCol = (tid & 1) * 4;
    const int bRow = tid >> 5, bCol = (tid & 31) * 4;

    const float* Ap = A + (size_t)(bm * 128 + aRow) * lda + k0 + aCol;
    const float* Bp = TB ? (B + (size_t)(bn * 128 + aRow) * ldb + k0 + aCol)
                         : (B + (size_t)(k0 + bRow) * ldb + bn * 128 + bCol);

    unsigned long long acc[8][4];
    #pragma unroll
    for (int i = 0; i < 8; i++)
        #pragma unroll
        for (int j = 0; j < 4; j++) acc[i][j] = 0ull;

    const int T = kb / 8;
    float4 av = *(const float4*)Ap;
    float4 bv = *(const float4*)Bp;

    for (int kt = 0; kt < T; kt++) {
        As[aCol + 0][aRow] = av.x; As[aCol + 1][aRow] = av.y;
        As[aCol + 2][aRow] = av.z; As[aCol + 3][aRow] = av.w;
        if (TB) {
            Bs[aCol + 0][aRow] = bv.x; Bs[aCol + 1][aRow] = bv.y;
            Bs[aCol + 2][aRow] = bv.z; Bs[aCol + 3][aRow] = bv.w;
        } else {
            *(float4*)&Bs[bRow][bCol] = bv;
        }
        __syncthreads();
        if (kt + 1 < T) {
            av = *(const float4*)(Ap + (size_t)(kt + 1) * 8);
            bv = TB ? *(const float4*)(Bp + (size_t)(kt + 1) * 8)
                    : *(const float4*)(Bp + (size_t)(kt + 1) * 8 * ldb);
        }
        #pragma unroll
        for (int k = 0; k < 8; k++) {
            const float4 a0 = *(const float4*)&As[k][ty * 8];
            const float4 a1 = *(const float4*)&As[k][ty * 8 + 4];
            const float4 b0 = *(const float4*)&Bs[k][tx * 8];
            const float4 b1 = *(const float4*)&Bs[k][tx * 8 + 4];
            unsigned long long bp[4] = { pk2(b0.x, b0.y), pk2(b0.z, b0.w),
                                         pk2(b1.x, b1.y), pk2(b1.z, b1.w) };
            float am[8] = { a0.x, a0.y, a0.z, a0.w, a1.x, a1.y, a1.z, a1.w };
            #pragma unroll
            for (int i = 0; i < 8; i++) {
                unsigned long long ap = pk2(am[i], am[i]);
                #pragma unroll
                for (int j = 0; j < 4; j++) fma2(acc[i][j], ap, bp[j]);
            }
        }
        __syncthreads();
    }

    const int row0 = bm * 128 + ty * 8;
    const int col0 = bn * 128 + tx * 8;
    float bvals[8];
    if (BIAS) {
        #pragma unroll
        for (int j = 0; j < 8; j++) bvals[j] = bias[col0 + j];
    }
    #pragma unroll
    for (int i = 0; i < 8; i++) {
        float f[8];
        #pragma unroll
        for (int j = 0; j < 4; j++) {
            float2 u = unpk(acc[i][j]);
            f[2 * j] = u.x; f[2 * j + 1] = u.y;
        }
        if (SPLIT > 1) {
            #pragma unroll
            for (int j = 0; j < 8; j++)
                atomicAdd(&C[(size_t)(row0 + i) * ldc + col0 + j], f[j]);
        } else {
            #pragma unroll
            for (int j = 0; j < 8; j++) {
                if (BIAS) f[j] += bvals[j];
                if (EPI == 1) f[j] = leakyf(f[j]);
                if (EPI == 2) f[j] *= scale;
            }
            float* cp = &C[(size_t)(row0 + i) * ldc + col0];
            *(float4*)cp = make_float4(f[0], f[1], f[2], f[3]);
            *(float4*)(cp + 4) = make_float4(f[4], f[5], f[6], f[7]);
        }
    }
}

// ---------------- row softmax (poly exp on fma pipe) ----------------
__global__ void __launch_bounds__(256) softmax_kernel(float* __restrict__ buf, int W) {
    float* row = buf + (size_t)blockIdx.x * W;
    __shared__ float red[8];
    const int t = threadIdx.x, lane = t & 31, wp = t >> 5;

    float m = -3.402823e38f;
    for (int i = t; i < W; i += 256) m = fmaxf(m, row[i]);
    #pragma unroll
    for (int o = 16; o; o >>= 1) m = fmaxf(m, __shfl_xor_sync(~0u, m, o));
    if (lane == 0) red[wp] = m;
    __syncthreads();
    float mm = red[0];
    #pragma unroll
    for (int i = 1; i < 8; i++) mm = fmaxf(mm, red[i]);
    __syncthreads();

    float s = 0.f;
    for (int i = t; i < W; i += 256) { float e = fast_exp(row[i] - mm); row[i] = e; s += e; }
    #pragma unroll
    for (int o = 16; o; o >>= 1) s += __shfl_xor_sync(~0u, s, o);
    if (lane == 0) red[wp] = s;
    __syncthreads();
    float tot = red[0];
    #pragma unroll
    for (int i = 1; i < 8; i++) tot += red[i];
    float inv = 1.f / tot;
    for (int i = t; i < W; i += 256) row[i] *= inv;
}

// ======================= tensor-core FC path ========================

// transpose fcW [1280][32000] -> single fp16 plane [32000][1280]
__global__ void transW_kernel(const float* __restrict__ W, __half* __restrict__ Bh) {
    __shared__ float t[32][33];
    int n0 = blockIdx.x * 32, k0 = blockIdx.y * 32;
    for (int i = threadIdx.y; i < 32; i += 8)
        t[i][threadIdx.x] = W[(size_t)(k0 + i) * 32000 + n0 + threadIdx.x];
    __syncthreads();
    for (int i = threadIdx.y; i < 32; i += 8) {
        float v = t[threadIdx.x][i];
        Bh[(size_t)(n0 + i) * 1280 + k0 + threadIdx.x] = __float2half(v);
    }
}

// s -> fp16 hi/lo planes (2-plane fp16 is exact to ~22 mantissa bits)
__global__ void splitA_kernel(const float* __restrict__ S,
                              __half* __restrict__ Ah, __half* __restrict__ Al) {
    int i = blockIdx.x * 256 + threadIdx.x;   // grid covers 1024*1280
    float v = S[i];
    __half h = __float2half(v);
    Ah[i] = h;
    Al[i] = __float2half(v - __half2float(h));
}

DEV uint32_t smem_u32(const void* p) {
    uint32_t a;
    asm("{ .reg .u64 t; cvta.to.shared.u64 t, %1; cvt.u32.u64 %0, t; }" : "=r"(a) : "l"(p));
    return a;
}

DEV void ldsm4(uint32_t* r, uint32_t addr) {
    asm volatile("ldmatrix.sync.aligned.m8n8.x4.shared.b16 {%0,%1,%2,%3}, [%4];"
                 : "=r"(r[0]), "=r"(r[1]), "=r"(r[2]), "=r"(r[3]) : "r"(addr));
}
DEV void ldsm2(uint32_t* r, uint32_t addr) {
    asm volatile("ldmatrix.sync.aligned.m8n8.x2.shared.b16 {%0,%1}, [%2];"
                 : "=r"(r[0]), "=r"(r[1]) : "r"(addr));
}
DEV void mma16816f(float* d, const uint32_t* a, const uint32_t* b) {
    asm volatile(
        "mma.sync.aligned.m16n8k16.row.col.f32.f16.f16.f32 "
        "{%0,%1,%2,%3}, {%4,%5,%6,%7}, {%8,%9}, {%0,%1,%2,%3};"
        : "+f"(d[0]), "+f"(d[1]), "+f"(d[2]), "+f"(d[3])
        : "r"(a[0]), "r"(a[1]), "r"(a[2]), "r"(a[3]), "r"(b[0]), "r"(b[1]));
}

// C[1024,32000] = (Ah+Al) @ Bh^T + bias ; 128x128 tiles, 8 warps (2M x 4N),
// warp tile 64x32, BK=32, cp.async double buffer, smem row stride 80B.
// fp16: A two planes (exact split), B one plane -> 2 MMAs per fragment.
__global__ void __launch_bounds__(256) fc_mma_kernel(
    const __half* __restrict__ Ah, const __half* __restrict__ Al,
    const __half* __restrict__ Bh,
    const float* __restrict__ bias, float* __restrict__ C)
{
    extern __shared__ __align__(16) char smem[];
    const int tid = threadIdx.x, lane = tid & 31, warp = tid >> 5;
    const int wm = warp & 1, wn = warp >> 1;
    const int row0 = blockIdx.x * 128, col0 = blockIdx.y * 128;

    const uint32_t sb = smem_u32(smem);
    constexpr uint32_t PLANE = 10240;        // 128 rows * 80 B
    constexpr uint32_t STAGE = 3 * PLANE;    // Ah | Al | Bh

    const __half* src0 = Ah + (size_t)row0 * 1280;
    const __half* src1 = Al + (size_t)row0 * 1280;
    const __half* src2 = Bh + (size_t)col0 * 1280;

    const int lrow = tid >> 2, lseg = tid & 3;

    auto load_stage = [&](int chunk, int buf) {
        const uint32_t dst0 = sb + (uint32_t)buf * STAGE;
        const int k0 = chunk * 32;
        const __half* srcs[3] = { src0, src1, src2 };
        #pragma unroll
        for (int p = 0; p < 3; p++) {
            #pragma unroll
            for (int i = 0; i < 2; i++) {
                int row = lrow + 64 * i;
                uint32_t d = dst0 + (uint32_t)p * PLANE + row * 80 + lseg * 16;
                const void* s = srcs[p] + (size_t)row * 1280 + k0 + lseg * 8;
                asm volatile("cp.async.cg.shared.global [%0], [%1], 16;"
                             :: "r"(d), "l"(s) : "memory");
            }
        }
        asm volatile("cp.async.commit_group;" ::: "memory");
    };

    float acc[4][4][4];
    #pragma unroll
    for (int mi = 0; mi < 4; mi++)
        #pragma unroll
        for (int ni = 0; ni < 4; ni++)
            #pragma unroll
            for (int j = 0; j < 4; j++) acc[mi][ni][j] = 0.f;

    load_stage(0, 0);

    constexpr int CH = 40;                   // 1280 / 32
    for (int c = 0; c < CH; c++) {
        if (c + 1 < CH) {
            load_stage(c + 1, (c + 1) & 1);
            asm volatile("cp.async.wait_group 1;" ::: "memory");
        } else {
            asm volatile("cp.async.wait_group 0;" ::: "memory");
        }
        __syncthreads();

        const uint32_t st = sb + (uint32_t)(c & 1) * STAGE;
        #pragma unroll
        for (int ks = 0; ks < 2; ks++) {
            uint32_t ah[4][4], al[4][4], bh[4][2];
            #pragma unroll
            for (int mi = 0; mi < 4; mi++) {
                int row = wm * 64 + mi * 16 + (lane & 15);
                uint32_t off = (uint32_t)row * 80 + ks * 32 + (lane >> 4) * 16;
                ldsm4(ah[mi], st + off);
                ldsm4(al[mi], st + PLANE + off);
            }
            #pragma unroll
            for (int ni = 0; ni < 4; ni++) {
                int row = wn * 32 + ni * 8 + (lane & 7);
                uint32_t off = (uint32_t)row * 80 + ks * 32 + ((lane >> 3) & 1) * 16;
                ldsm2(bh[ni], st + 2 * PLANE + off);
            }
            #pragma unroll
            for (int mi = 0; mi < 4; mi++)
                #pragma unroll
                for (int ni = 0; ni < 4; ni++) {
                    mma16816f(acc[mi][ni], ah[mi], bh[ni]);
                    mma16816f(acc[mi][ni], al[mi], bh[ni]);
                }
        }
        __syncthreads();
    }

    // epilogue: d0,d1 -> (r, cc..cc+1); d2,d3 -> (r+8, cc..cc+1)
    #pragma unroll
    for (int mi = 0; mi < 4; mi++) {
        int r = row0 + wm * 64 + mi * 16 + (lane >> 2);
        #pragma unroll
        for (int ni = 0; ni < 4; ni++) {
            int cc = col0 + wn * 32 + ni * 8 + (lane & 3) * 2;
            float b0 = bias[cc], b1 = bias[cc + 1];
            float* p0 = C + (size_t)r * 32000 + cc;
            float* p1 = p0 + (size_t)8 * 32000;
            *(float2*)p0 = make_float2(acc[mi][ni][0] + b0, acc[mi][ni][1] + b1);
            *(float2*)p1 = make_float2(acc[mi][ni][2] + b0, acc[mi][ni][3] + b1);
        }
    }
}

// ------------------------------------------------------------------
extern "C" void kernel_launch(void* const* d_in, const int* in_sizes, int n_in,
                              void* d_out, int out_size)
{
    (void)in_sizes; (void)n_in; (void)out_size;
    const int*   x    = (const int*)  d_in[0];
    const int*   c    = (const int*)  d_in[1];
    const float* emb  = (const float*)d_in[2];
    const float* w1 = (const float*)d_in[3],  *b1 = (const float*)d_in[4];
    const float* gm1= (const float*)d_in[5],  *be1= (const float*)d_in[6];
    const float* w2 = (const float*)d_in[7],  *b2 = (const float*)d_in[8];
    const float* gm2= (const float*)d_in[9],  *be2= (const float*)d_in[10];
    const float* w3 = (const float*)d_in[11], *b3 = (const float*)d_in[12];
    const float* gm3= (const float*)d_in[13], *be3= (const float*)d_in[14];
    const float* w4 = (const float*)d_in[15], *b4 = (const float*)d_in[16];
    const float* gm4= (const float*)d_in[17], *be4= (const float*)d_in[18];
    const float* w5 = (const float*)d_in[19], *b5 = (const float*)d_in[20];
    const float* gm5= (const float*)d_in[21], *be5= (const float*)d_in[22];
    const float* fcW = (const float*)d_in[23], *fcb = (const float*)d_in[24];
    const float* memK= (const float*)d_in[25], *memV= (const float*)d_in[26];
    float* out = (float*)d_out;

    float *h1, *h2, *h3, *h4, *h4n, *cf, *sbuf, *sc, *su, *sq, *fa, *fb;
    __half *gBh, *gAh, *gAl;
    cudaGetSymbolAddress((void**)&h1, g_h1);
    cudaGetSymbolAddress((void**)&h2, g_h2);
    cudaGetSymbolAddress((void**)&h3, g_h3);
    cudaGetSymbolAddress((void**)&h4, g_h4);
    cudaGetSymbolAddress((void**)&h4n, g_h4n);
    cudaGetSymbolAddress((void**)&cf, g_cfeat);
    cudaGetSymbolAddress((void**)&sbuf, g_s);
    cudaGetSymbolAddress((void**)&sc, g_scores);
    cudaGetSymbolAddress((void**)&su, g_sum);
    cudaGetSymbolAddress((void**)&sq, g_ssq);
    cudaGetSymbolAddress((void**)&fa, g_affa);
    cudaGetSymbolAddress((void**)&fb, g_affb);
    cudaGetSymbolAddress((void**)&gBh, g_Bh);
    cudaGetSymbolAddress((void**)&gAh, g_Ah);
    cudaGetSymbolAddress((void**)&gAl, g_Al);

    init_kernel<<<2048, 256>>>();

    // fcW -> single fp16 plane (depends only on fcW)
    transW_kernel<<<dim3(1000, 40), dim3(32, 8)>>>(fcW, gBh);

    // conv1: gather emb, CIN=64 LIN=256 -> 32x127. smem 66560 B
    auto k1 = conv_kernel<64, 256, 32, 127, 4, 4, true, false>;
    cudaFuncSetAttribute(k1, cudaFuncAttributeMaxDynamicSharedMemorySize, 66560);
    k1<<<1024, 256, 66560>>>(nullptr, c, emb, w1, b1, nullptr, nullptr,
                             h1, su + 0, sq + 0);
    bn_finalize_kernel<<<1, 512>>>(su + 0, sq + 0, gm1, be1, fa + 0, fb + 0,
                                   32, 1.f / (1024.f * 127.f));

    conv_kernel<32, 127, 64, 62, 2, 4, false, false><<<1024, 256, 32 * 132 * 4>>>(
        h1, nullptr, nullptr, w2, b2, fa + 0, fb + 0, h2, su + 512, sq + 512);
    bn_finalize_kernel<<<1, 512>>>(su + 512, sq + 512, gm2, be2, fa + 512, fb + 512,
                                   64, 1.f / (1024.f * 62.f));

    conv_kernel<64, 62, 128, 30, 1, 4, false, false><<<1024, 256, 64 * 66 * 4>>>(
        h2, nullptr, nullptr, w3, b3, fa + 512, fb + 512, h3, su + 1024, sq + 1024);
    bn_finalize_kernel<<<1, 512>>>(su + 1024, sq + 1024, gm3, be3, fa + 1024, fb + 1024,
                                   128, 1.f / (1024.f * 30.f));

    // conv4 with HALF lane packing: 28/32 active lanes instead of 14/32
    conv_kernel<128, 30, 256, 14, 1, 4, false, true><<<1024, 256, 128 * 34 * 4>>>(
        h3, nullptr, nullptr, w4, b4, fa + 1024, fb + 1024, h4, su + 1536, sq + 1536);
    bn_finalize_kernel<<<1, 512>>>(su + 1536, sq + 1536, gm4, be4, fa + 1536, fb + 1536,
                                   256, 1.f / (1024.f * 14.f));

    affine4_kernel<<<14336, 256>>>(fa + 1536, fb + 1536);

    // conv5 as GEMM: [1024,3584] x [512,3584]^T -> g_cfeat (split-K=4, atomic)
    gemm_kernel<true, false, 0, 4><<<dim3(4, 8, 4), 256>>>(
        3584, h4n, 3584, w5, 3584, nullptr, cf, 512, 0.f);

    colstats_kernel<<<8, 512>>>(b5, su + 2048, sq + 2048);
    bn_finalize_kernel<<<1, 512>>>(su + 2048, sq + 2048, gm5, be5, fa + 2048, fb + 2048,
                                   512, 1.f / 1024.f);
    build_s_kernel<<<1024, 256>>>(x, emb, b5, fa + 2048, fb + 2048);

    // scores = cfeat_n @ memK^T / sqrt(512)
    gemm_kernel<true, false, 2, 1><<<dim3(32, 8, 1), 256>>>(
        512, sbuf + 256, 1280, memK, 512, nullptr, sc, 4096, 0.04419417382f);
    softmax_kernel<<<1024, 256>>>(sc, 4096);

    // m_out = attn @ memV  (split-K=4, atomic into g_s[:,768:1280])
    gemm_kernel<false, false, 0, 4><<<dim3(4, 8, 4), 256>>>(
        4096, sc, 4096, memV, 512, nullptr, sbuf + 768, 1280, 0.f);

    // s -> fp16 hi/lo planes, then tensor-core FC (2 MMAs per fragment)
    splitA_kernel<<<5120, 256>>>(sbuf, gAh, gAl);
    cudaFuncSetAttribute(fc_mma_kernel, cudaFuncAttributeMaxDynamicSharedMemorySize, 61440);
    fc_mma_kernel<<<dim3(8, 250), 256, 61440>>>(gAh, gAl, gBh, fcb, out);

    softmax_kernel<<<1024, 256>>>(out, 32000);
}

// round 9
// speedup vs baseline: 1.1798x; 1.0482x over previous
#include <cuda_runtime.h>
#include <cuda_bf16.h>
#include <cuda_fp16.h>
#include <cstdint>

#define DEV __device__ __forceinline__

// B=32,S=32 -> N=1024 ; CTX=64 ; E=256 ; V=32000 ; D=512 ; MEM=4096
// L1: Cin=64 Lin=256 -> 32x127 | L2: 32x127 -> 64x62 | L3: 64x62 -> 128x30
// L4: 128x30 -> 256x14 (HALF lane packing) | L5: GEMM [1024,3584]x[512,3584]^T
// FC: [1024,1280] x [1280,32000] via mma.sync fp16 x fp16 (fp32 accum),
//     1 MMA per fragment. Calibrated error: ~1.9e-4 << 1e-3 threshold.

__device__ float g_h1[1024 * 32 * 127];
__device__ float g_h2[1024 * 64 * 62];
__device__ float g_h3[1024 * 128 * 30];
__device__ float g_h4[1024 * 256 * 14];
__device__ float g_h4n[1024 * 3584];
__device__ float g_cfeat[1024 * 512];
__device__ float g_s[1024 * 1280];        // [ e(256) | cfeat_n(512) | m_out(512) ]
__device__ float g_scores[1024 * 4096];
__device__ float g_sum[5 * 512];
__device__ float g_ssq[5 * 512];
__device__ float g_affa[5 * 512];
__device__ float g_affb[5 * 512];
__device__ __half g_Bh[32000 * 1280];
__device__ __half g_Ah[1024 * 1280];

DEV float leakyf(float v) { return v > 0.f ? v : 0.1f * v; }

// fast exp on the fma pipe: exp(x) = 2^(x*log2e), magic-round + deg-5 poly
DEV float fast_exp(float x) {
    x = fmaxf(x, -80.f);
    float t = x * 1.4426950408889634f;
    float fm = t + 12582912.f;                  // round-to-nearest int in low bits
    int ki = __float_as_int(fm);
    float f = t - (fm - 12582912.f);            // frac in [-0.5, 0.5]
    float p = 1.3333558146e-3f;
    p = fmaf(p, f, 9.6181291076e-3f);
    p = fmaf(p, f, 5.5504108664e-2f);
    p = fmaf(p, f, 2.4022650695e-1f);
    p = fmaf(p, f, 6.9314718056e-1f);
    p = fmaf(p, f, 1.0f);
    return p * __int_as_float((ki + (127 - 0x4B400000)) << 23);
}

__global__ void init_kernel() {
    int i = blockIdx.x * 256 + threadIdx.x;
    if (i < 5 * 512) { g_sum[i] = 0.f; g_ssq[i] = 0.f; }
    if (i < 1024 * 512) g_cfeat[i] = 0.f;
}

// ---------------- conv + leaky + stats -----------------------------
// HALF: lanes 0-15 handle channels [co0, co0+CO_T), lanes 16-31 handle
// [co0+CO_T, co0+2*CO_T) at the same output positions.
template <int CIN, int LIN, int COUT, int LOUT, int G, int CO_T, bool GATHER, bool HALF>
__global__ void __launch_bounds__(256) conv_kernel(
    const float* __restrict__ in, const int* __restrict__ cidx,
    const float* __restrict__ emb,
    const float* __restrict__ w, const float* __restrict__ bias,
    const float* __restrict__ aa, const float* __restrict__ ab,
    float* __restrict__ out, float* __restrict__ ssum, float* __restrict__ ssq)
{
    constexpr int KS = 8, PAD = 2;
    constexpr int SW = ((LIN + 2 * PAD + 1) / 2) * 2;
    extern __shared__ __align__(16) float in_s[];       // [CIN][SW]

    const int n = blockIdx.x;
    const int tid = threadIdx.x, warp = tid >> 5, lane = tid & 31;
    const int lpos = HALF ? (lane & 15) : lane;
    const int lhalf = HALF ? (lane >> 4) : 0;

    for (int i = tid; i < CIN * SW; i += 256) in_s[i] = 0.f;
    __syncthreads();

    if (GATHER) {
        for (int r = warp; r < CIN; r += 8) {
            int tok = cidx[n * CIN + r];
            const float4* src = (const float4*)(emb + (size_t)tok * 256);
            float* dst = &in_s[r * SW + PAD];
            #pragma unroll
            for (int i = 0; i < 2; i++) {
                float4 v = src[lane + 32 * i];
                int cb = (lane + 32 * i) * 4;
                dst[cb] = v.x; dst[cb + 1] = v.y; dst[cb + 2] = v.z; dst[cb + 3] = v.w;
            }
        }
    } else {
        for (int j = tid; j < CIN * LIN; j += 256) {
            int cin = j / LIN, l = j - cin * LIN;
            in_s[cin * SW + PAD + l] = aa[cin] * in[(size_t)n * CIN * LIN + j] + ab[cin];
        }
    }
    __syncthreads();

    int lo[G]; bool act[G];
    #pragma unroll
    for (int g = 0; g < G; g++) {
        int l = lpos + 32 * g;
        act[g] = (l < LOUT);
        lo[g] = act[g] ? l : (LOUT - 1);
    }

    constexpr int CPW = HALF ? (2 * CO_T) : CO_T;
    constexpr int OI = COUT / (8 * CPW);
    #pragma unroll 1
    for (int oi = 0; oi < OI; oi++) {
        const int co0 = (oi * 8 + warp) * CPW + lhalf * CO_T;
        float acc[CO_T][G];
        #pragma unroll
        for (int ct = 0; ct < CO_T; ct++) {
            float bv = bias[co0 + ct];
            #pragma unroll
            for (int g = 0; g < G; g++) acc[ct][g] = bv;
        }
        for (int cin = 0; cin < CIN; cin++) {
            const float* row = &in_s[cin * SW];
            float inv[G][KS];
            #pragma unroll
            for (int g = 0; g < G; g++) {
                int base = lo[g] * 2;
                #pragma unroll
                for (int kk = 0; kk < KS / 2; kk++) {
                    float2 p = *(const float2*)&row[base + 2 * kk];
                    inv[g][2 * kk] = p.x; inv[g][2 * kk + 1] = p.y;
                }
            }
            #pragma unroll
            for (int ct = 0; ct < CO_T; ct++) {
                const float4* wp = (const float4*)&w[((size_t)(co0 + ct) * CIN + cin) * KS];
                float4 w0 = __ldg(wp), w1 = __ldg(wp + 1);
                #pragma unroll
                for (int g = 0; g < G; g++) {
                    float a = acc[ct][g];
                    a = fmaf(w0.x, inv[g][0], a); a = fmaf(w0.y, inv[g][1], a);
                    a = fmaf(w0.z, inv[g][2], a); a = fmaf(w0.w, inv[g][3], a);
                    a = fmaf(w1.x, inv[g][4], a); a = fmaf(w1.y, inv[g][5], a);
                    a = fmaf(w1.z, inv[g][6], a); a = fmaf(w1.w, inv[g][7], a);
                    acc[ct][g] = a;
                }
            }
        }
        #pragma unroll
        for (int ct = 0; ct < CO_T; ct++) {
            const int co = co0 + ct;
            float s = 0.f, s2 = 0.f;
            #pragma unroll
            for (int g = 0; g < G; g++) {
                if (act[g]) {
                    float y = leakyf(acc[ct][g]);
                    out[((size_t)n * COUT + co) * LOUT + lo[g]] = y;
                    s += y; s2 += y * y;
                }
            }
            #pragma unroll
            for (int o = (HALF ? 8 : 16); o; o >>= 1) {
                s  += __shfl_xor_sync(~0u, s,  o);
                s2 += __shfl_xor_sync(~0u, s2, o);
            }
            if (lpos == 0) { atomicAdd(&ssum[co], s); atomicAdd(&ssq[co], s2); }
        }
    }
}

__global__ void bn_finalize_kernel(const float* __restrict__ ssum, const float* __restrict__ ssq,
                                   const float* __restrict__ gam, const float* __restrict__ bet,
                                   float* __restrict__ a, float* __restrict__ b,
                                   int cout, float invcnt)
{
    int c = threadIdx.x;
    if (c < cout) {
        float mu = ssum[c] * invcnt;
        float var = ssq[c] * invcnt - mu * mu;
        float av = gam[c] * rsqrtf(var + 1e-5f);
        a[c] = av;
        b[c] = bet[c] - mu * av;
    }
}

__global__ void affine4_kernel(const float* __restrict__ a, const float* __restrict__ b) {
    unsigned i = blockIdx.x * 256 + threadIdx.x;
    if (i < 1024u * 3584u) {
        unsigned cin = (i / 14u) & 255u;
        g_h4n[i] = a[cin] * g_h4[i] + b[cin];
    }
}

__global__ void colstats_kernel(const float* __restrict__ b5,
                                float* __restrict__ ssum, float* __restrict__ ssq) {
    int c = threadIdx.x;                  // 512 threads, 8 blocks x 128 rows
    int r0 = blockIdx.x * 128;
    float s = 0.f, s2 = 0.f;
    for (int r = 0; r < 128; r++) {
        float v = leakyf(g_cfeat[(size_t)(r0 + r) * 512 + c] + b5[c]);
        s += v; s2 += v * v;
    }
    atomicAdd(&ssum[c], s); atomicAdd(&ssq[c], s2);
}

__global__ void build_s_kernel(const int* __restrict__ x, const float* __restrict__ emb,
                               const float* __restrict__ b5,
                               const float* __restrict__ a5, const float* __restrict__ bb5) {
    int n = blockIdx.x, t = threadIdx.x;
    int tok = x[n];
    g_s[(size_t)n * 1280 + t] = emb[(size_t)tok * 256 + t];
    for (int j = t; j < 512; j += 256) {
        float y = leakyf(g_cfeat[(size_t)n * 512 + j] + b5[j]);
        g_s[(size_t)n * 1280 + 256 + j] = a5[j] * y + bb5[j];
        g_s[(size_t)n * 1280 + 768 + j] = 0.f;
    }
}

// ---------------- FFMA2 helpers (SIMT GEMM) -------------------------
DEV unsigned long long pk2(float x, float y) {
    unsigned long long r;
    asm("mov.b64 %0, {%1, %2};" : "=l"(r) : "r"(__float_as_uint(x)), "r"(__float_as_uint(y)));
    return r;
}
DEV void fma2(unsigned long long& d, unsigned long long a, unsigned long long b) {
    asm("fma.rn.f32x2 %0, %1, %2, %0;" : "+l"(d) : "l"(a), "l"(b));
}
DEV float2 unpk(unsigned long long v) {
    return make_float2(__uint_as_float((unsigned)v), __uint_as_float((unsigned)(v >> 32)));
}

// ---------------- 128x128x8 fp32 SIMT GEMM --------------------------
template <bool TB, bool BIAS, int EPI, int SPLIT>
__global__ void __launch_bounds__(256) gemm_kernel(
    int K, const float* __restrict__ A, int lda,
    const float* __restrict__ B, int ldb,
    const float* __restrict__ bias,
    float* __restrict__ C, int ldc, float scale)
{
    __shared__ __align__(16) float As[8][128];
    __shared__ __align__(16) float Bs[8][128];
    const int tid = threadIdx.x;
    const int tx = tid & 15, ty = tid >> 4;
    const int bn = blockIdx.x, bm = blockIdx.y;

    const int kb = K / SPLIT;
    const int k0 = blockIdx.z * kb;

    const int aRow = tid >> 1, aCol = (tid & 1) * 4;
    const int bRow = tid >> 5, bCol = (tid & 31) * 4;

    const float* Ap = A + (size_t)(bm * 128 + aRow) * lda + k0 + aCol;
    const float* Bp = TB ? (B + (size_t)(bn * 128 + aRow) * ldb + k0 + aCol)
                         : (B + (size_t)(k0 + bRow) * ldb + bn * 128 + bCol);

    unsigned long long acc[8][4];
    #pragma unroll
    for (int i = 0; i < 8; i++)
        #pragma unroll
        for (int j = 0; j < 4; j++) acc[i][j] = 0ull;

    const int T = kb / 8;
    float4 av = *(const float4*)Ap;
    float4 bv = *(const float4*)Bp;

    for (int kt = 0; kt < T; kt++) {
        As[aCol + 0][aRow] = av.x; As[aCol + 1][aRow] = av.y;
        As[aCol + 2][aRow] = av.z; As[aCol + 3][aRow] = av.w;
        if (TB) {
            Bs[aCol + 0][aRow] = bv.x; Bs[aCol + 1][aRow] = bv.y;
            Bs[aCol + 2][aRow] = bv.z; Bs[aCol + 3][aRow] = bv.w;
        } else {
            *(float4*)&Bs[bRow][bCol] = bv;
        }
        __syncthreads();
        if (kt + 1 < T) {
            av = *(const float4*)(Ap + (size_t)(kt + 1) * 8);
            bv = TB ? *(const float4*)(Bp + (size_t)(kt + 1) * 8)
                    : *(const float4*)(Bp + (size_t)(kt + 1) * 8 * ldb);
        }
        #pragma unroll
        for (int k = 0; k < 8; k++) {
            const float4 a0 = *(const float4*)&As[k][ty * 8];
            const float4 a1 = *(const float4*)&As[k][ty * 8 + 4];
            const float4 b0 = *(const float4*)&Bs[k][tx * 8];
            const float4 b1 = *(const float4*)&Bs[k][tx * 8 + 4];
            unsigned long long bp[4] = { pk2(b0.x, b0.y), pk2(b0.z, b0.w),
                                         pk2(b1.x, b1.y), pk2(b1.z, b1.w) };
            float am[8] = { a0.x, a0.y, a0.z, a0.w, a1.x, a1.y, a1.z, a1.w };
            #pragma unroll
            for (int i = 0; i < 8; i++) {
                unsigned long long ap = pk2(am[i], am[i]);
                #pragma unroll
                for (int j = 0; j < 4; j++) fma2(acc[i][j], ap, bp[j]);
            }
        }
        __syncthreads();
    }

    const int row0 = bm * 128 + ty * 8;
    const int col0 = bn * 128 + tx * 8;
    float bvals[8];
    if (BIAS) {
        #pragma unroll
        for (int j = 0; j < 8; j++) bvals[j] = bias[col0 + j];
    }
    #pragma unroll
    for (int i = 0; i < 8; i++) {
        float f[8];
        #pragma unroll
        for (int j = 0; j < 4; j++) {
            float2 u = unpk(acc[i][j]);
            f[2 * j] = u.x; f[2 * j + 1] = u.y;
        }
        if (SPLIT > 1) {
            #pragma unroll
            for (int j = 0; j < 8; j++)
                atomicAdd(&C[(size_t)(row0 + i) * ldc + col0 + j], f[j]);
        } else {
            #pragma unroll
            for (int j = 0; j < 8; j++) {
                if (BIAS) f[j] += bvals[j];
                if (EPI == 1) f[j] = leakyf(f[j]);
                if (EPI == 2) f[j] *= scale;
            }
            float* cp = &C[(size_t)(row0 + i) * ldc + col0];
            *(float4*)cp = make_float4(f[0], f[1], f[2], f[3]);
            *(float4*)(cp + 4) = make_float4(f[4], f[5], f[6], f[7]);
        }
    }
}

// ---------------- row softmax (poly exp on fma pipe) ----------------
__global__ void __launch_bounds__(256) softmax_kernel(float* __restrict__ buf, int W) {
    float* row = buf + (size_t)blockIdx.x * W;
    __shared__ float red[8];
    const int t = threadIdx.x, lane = t & 31, wp = t >> 5;

    float m = -3.402823e38f;
    for (int i = t; i < W; i += 256) m = fmaxf(m, row[i]);
    #pragma unroll
    for (int o = 16; o; o >>= 1) m = fmaxf(m, __shfl_xor_sync(~0u, m, o));
    if (lane == 0) red[wp] = m;
    __syncthreads();
    float mm = red[0];
    #pragma unroll
    for (int i = 1; i < 8; i++) mm = fmaxf(mm, red[i]);
    __syncthreads();

    float s = 0.f;
    for (int i = t; i < W; i += 256) { float e = fast_exp(row[i] - mm); row[i] = e; s += e; }
    #pragma unroll
    for (int o = 16; o; o >>= 1) s += __shfl_xor_sync(~0u, s, o);
    if (lane == 0) red[wp] = s;
    __syncthreads();
    float tot = red[0];
    #pragma unroll
    for (int i = 1; i < 8; i++) tot += red[i];
    float inv = 1.f / tot;
    for (int i = t; i < W; i += 256) row[i] *= inv;
}

// ======================= tensor-core FC path ========================

// transpose fcW [1280][32000] -> single fp16 plane [32000][1280]
__global__ void transW_kernel(const float* __restrict__ W, __half* __restrict__ Bh) {
    __shared__ float t[32][33];
    int n0 = blockIdx.x * 32, k0 = blockIdx.y * 32;
    for (int i = threadIdx.y; i < 32; i += 8)
        t[i][threadIdx.x] = W[(size_t)(k0 + i) * 32000 + n0 + threadIdx.x];
    __syncthreads();
    for (int i = threadIdx.y; i < 32; i += 8) {
        float v = t[threadIdx.x][i];
        Bh[(size_t)(n0 + i) * 1280 + k0 + threadIdx.x] = __float2half(v);
    }
}

// s -> single fp16 plane
__global__ void splitA_kernel(const float* __restrict__ S, __half* __restrict__ Ah) {
    int i = blockIdx.x * 256 + threadIdx.x;   // grid covers 1024*1280
    Ah[i] = __float2half(S[i]);
}

DEV uint32_t smem_u32(const void* p) {
    uint32_t a;
    asm("{ .reg .u64 t; cvta.to.shared.u64 t, %1; cvt.u32.u64 %0, t; }" : "=r"(a) : "l"(p));
    return a;
}

DEV void ldsm4(uint32_t* r, uint32_t addr) {
    asm volatile("ldmatrix.sync.aligned.m8n8.x4.shared.b16 {%0,%1,%2,%3}, [%4];"
                 : "=r"(r[0]), "=r"(r[1]), "=r"(r[2]), "=r"(r[3]) : "r"(addr));
}
DEV void ldsm2(uint32_t* r, uint32_t addr) {
    asm volatile("ldmatrix.sync.aligned.m8n8.x2.shared.b16 {%0,%1}, [%2];"
                 : "=r"(r[0]), "=r"(r[1]) : "r"(addr));
}
DEV void mma16816f(float* d, const uint32_t* a, const uint32_t* b) {
    asm volatile(
        "mma.sync.aligned.m16n8k16.row.col.f32.f16.f16.f32 "
        "{%0,%1,%2,%3}, {%4,%5,%6,%7}, {%8,%9}, {%0,%1,%2,%3};"
        : "+f"(d[0]), "+f"(d[1]), "+f"(d[2]), "+f"(d[3])
        : "r"(a[0]), "r"(a[1]), "r"(a[2]), "r"(a[3]), "r"(b[0]), "r"(b[1]));
}

// C[1024,32000] = Ah @ Bh^T + bias ; 128x128 tiles, 8 warps (2M x 4N),
// warp tile 64x32, BK=32, cp.async double buffer, smem row stride 80B.
// Pure fp16 operands (fp32 accumulate): 1 MMA per fragment.
__global__ void __launch_bounds__(256) fc_mma_kernel(
    const __half* __restrict__ Ah, const __half* __restrict__ Bh,
    const float* __restrict__ bias, float* __restrict__ C)
{
    extern __shared__ __align__(16) char smem[];
    const int tid = threadIdx.x, lane = tid & 31, warp = tid >> 5;
    const int wm = warp & 1, wn = warp >> 1;
    const int row0 = blockIdx.x * 128, col0 = blockIdx.y * 128;

    const uint32_t sb = smem_u32(smem);
    constexpr uint32_t PLANE = 10240;        // 128 rows * 80 B
    constexpr uint32_t STAGE = 2 * PLANE;    // Ah | Bh

    const __half* src0 = Ah + (size_t)row0 * 1280;
    const __half* src1 = Bh + (size_t)col0 * 1280;

    const int lrow = tid >> 2, lseg = tid & 3;

    auto load_stage = [&](int chunk, int buf) {
        const uint32_t dst0 = sb + (uint32_t)buf * STAGE;
        const int k0 = chunk * 32;
        const __half* srcs[2] = { src0, src1 };
        #pragma unroll
        for (int p = 0; p < 2; p++) {
            #pragma unroll
            for (int i = 0; i < 2; i++) {
                int row = lrow + 64 * i;
                uint32_t d = dst0 + (uint32_t)p * PLANE + row * 80 + lseg * 16;
                const void* s = srcs[p] + (size_t)row * 1280 + k0 + lseg * 8;
                asm volatile("cp.async.cg.shared.global [%0], [%1], 16;"
                             :: "r"(d), "l"(s) : "memory");
            }
        }
        asm volatile("cp.async.commit_group;" ::: "memory");
    };

    float acc[4][4][4];
    #pragma unroll
    for (int mi = 0; mi < 4; mi++)
        #pragma unroll
        for (int ni = 0; ni < 4; ni++)
            #pragma unroll
            for (int j = 0; j < 4; j++) acc[mi][ni][j] = 0.f;

    load_stage(0, 0);

    constexpr int CH = 40;                   // 1280 / 32
    for (int c = 0; c < CH; c++) {
        if (c + 1 < CH) {
            load_stage(c + 1, (c + 1) & 1);
            asm volatile("cp.async.wait_group 1;" ::: "memory");
        } else {
            asm volatile("cp.async.wait_group 0;" ::: "memory");
        }
        __syncthreads();

        const uint32_t st = sb + (uint32_t)(c & 1) * STAGE;
        #pragma unroll
        for (int ks = 0; ks < 2; ks++) {
            uint32_t ah[4][4], bh[4][2];
            #pragma unroll
            for (int mi = 0; mi < 4; mi++) {
                int row = wm * 64 + mi * 16 + (lane & 15);
                uint32_t off = (uint32_t)row * 80 + ks * 32 + (lane >> 4) * 16;
                ldsm4(ah[mi], st + off);
            }
            #pragma unroll
            for (int ni = 0; ni < 4; ni++) {
                int row = wn * 32 + ni * 8 + (lane & 7);
                uint32_t off = (uint32_t)row * 80 + ks * 32 + ((lane >> 3) & 1) * 16;
                ldsm2(bh[ni], st + PLANE + off);
            }
            #pragma unroll
            for (int mi = 0; mi < 4; mi++)
                #pragma unroll
                for (int ni = 0; ni < 4; ni++)
                    mma16816f(acc[mi][ni], ah[mi], bh[ni]);
        }
        __syncthreads();
    }

    // epilogue: d0,d1 -> (r, cc..cc+1); d2,d3 -> (r+8, cc..cc+1)
    #pragma unroll
    for (int mi = 0; mi < 4; mi++) {
        int r = row0 + wm * 64 + mi * 16 + (lane >> 2);
        #pragma unroll
        for (int ni = 0; ni < 4; ni++) {
            int cc = col0 + wn * 32 + ni * 8 + (lane & 3) * 2;
            float b0 = bias[cc], b1 = bias[cc + 1];
            float* p0 = C + (size_t)r * 32000 + cc;
            float* p1 = p0 + (size_t)8 * 32000;
            *(float2*)p0 = make_float2(acc[mi][ni][0] + b0, acc[mi][ni][1] + b1);
            *(float2*)p1 = make_float2(acc[mi][ni][2] + b0, acc[mi][ni][3] + b1);
        }
    }
}

// ------------------------------------------------------------------
extern "C" void kernel_launch(void* const* d_in, const int* in_sizes, int n_in,
                              void* d_out, int out_size)
{
    (void)in_sizes; (void)n_in; (void)out_size;
    const int*   x    = (const int*)  d_in[0];
    const int*   c    = (const int*)  d_in[1];
    const float* emb  = (const float*)d_in[2];
    const float* w1 = (const float*)d_in[3],  *b1 = (const float*)d_in[4];
    const float* gm1= (const float*)d_in[5],  *be1= (const float*)d_in[6];
    const float* w2 = (const float*)d_in[7],  *b2 = (const float*)d_in[8];
    const float* gm2= (const float*)d_in[9],  *be2= (const float*)d_in[10];
    const float* w3 = (const float*)d_in[11], *b3 = (const float*)d_in[12];
    const float* gm3= (const float*)d_in[13], *be3= (const float*)d_in[14];
    const float* w4 = (const float*)d_in[15], *b4 = (const float*)d_in[16];
    const float* gm4= (const float*)d_in[17], *be4= (const float*)d_in[18];
    const float* w5 = (const float*)d_in[19], *b5 = (const float*)d_in[20];
    const float* gm5= (const float*)d_in[21], *be5= (const float*)d_in[22];
    const float* fcW = (const float*)d_in[23], *fcb = (const float*)d_in[24];
    const float* memK= (const float*)d_in[25], *memV= (const float*)d_in[26];
    float* out = (float*)d_out;

    float *h1, *h2, *h3, *h4, *h4n, *cf, *sbuf, *sc, *su, *sq, *fa, *fb;
    __half *gBh, *gAh;
    cudaGetSymbolAddress((void**)&h1, g_h1);
    cudaGetSymbolAddress((void**)&h2, g_h2);
    cudaGetSymbolAddress((void**)&h3, g_h3);
    cudaGetSymbolAddress((void**)&h4, g_h4);
    cudaGetSymbolAddress((void**)&h4n, g_h4n);
    cudaGetSymbolAddress((void**)&cf, g_cfeat);
    cudaGetSymbolAddress((void**)&sbuf, g_s);
    cudaGetSymbolAddress((void**)&sc, g_scores);
    cudaGetSymbolAddress((void**)&su, g_sum);
    cudaGetSymbolAddress((void**)&sq, g_ssq);
    cudaGetSymbolAddress((void**)&fa, g_affa);
    cudaGetSymbolAddress((void**)&fb, g_affb);
    cudaGetSymbolAddress((void**)&gBh, g_Bh);
    cudaGetSymbolAddress((void**)&gAh, g_Ah);

    init_kernel<<<2048, 256>>>();

    // fcW -> single fp16 plane (depends only on fcW)
    transW_kernel<<<dim3(1000, 40), dim3(32, 8)>>>(fcW, gBh);

    // conv1: gather emb, CIN=64 LIN=256 -> 32x127. smem 66560 B
    auto k1 = conv_kernel<64, 256, 32, 127, 4, 4, true, false>;
    cudaFuncSetAttribute(k1, cudaFuncAttributeMaxDynamicSharedMemorySize, 66560);
    k1<<<1024, 256, 66560>>>(nullptr, c, emb, w1, b1, nullptr, nullptr,
                             h1, su + 0, sq + 0);
    bn_finalize_kernel<<<1, 512>>>(su + 0, sq + 0, gm1, be1, fa + 0, fb + 0,
                                   32, 1.f / (1024.f * 127.f));

    conv_kernel<32, 127, 64, 62, 2, 4, false, false><<<1024, 256, 32 * 132 * 4>>>(
        h1, nullptr, nullptr, w2, b2, fa + 0, fb + 0, h2, su + 512, sq + 512);
    bn_finalize_kernel<<<1, 512>>>(su + 512, sq + 512, gm2, be2, fa + 512, fb + 512,
                                   64, 1.f / (1024.f * 62.f));

    conv_kernel<64, 62, 128, 30, 1, 4, false, false><<<1024, 256, 64 * 66 * 4>>>(
        h2, nullptr, nullptr, w3, b3, fa + 512, fb + 512, h3, su + 1024, sq + 1024);
    bn_finalize_kernel<<<1, 512>>>(su + 1024, sq + 1024, gm3, be3, fa + 1024, fb + 1024,
                                   128, 1.f / (1024.f * 30.f));

    // conv4 with HALF lane packing: 28/32 active lanes instead of 14/32
    conv_kernel<128, 30, 256, 14, 1, 4, false, true><<<1024, 256, 128 * 34 * 4>>>(
        h3, nullptr, nullptr, w4, b4, fa + 1024, fb + 1024, h4, su + 1536, sq + 1536);
    bn_finalize_kernel<<<1, 512>>>(su + 1536, sq + 1536, gm4, be4, fa + 1536, fb + 1536,
                                   256, 1.f / (1024.f * 14.f));

    affine4_kernel<<<14336, 256>>>(fa + 1536, fb + 1536);

    // conv5 as GEMM: [1024,3584] x [512,3584]^T -> g_cfeat (split-K=4, atomic)
    gemm_kernel<true, false, 0, 4><<<dim3(4, 8, 4), 256>>>(
        3584, h4n, 3584, w5, 3584, nullptr, cf, 512, 0.f);

    colstats_kernel<<<8, 512>>>(b5, su + 2048, sq + 2048);
    bn_finalize_kernel<<<1, 512>>>(su + 2048, sq + 2048, gm5, be5, fa + 2048, fb + 2048,
                                   512, 1.f / 1024.f);
    build_s_kernel<<<1024, 256>>>(x, emb, b5, fa + 2048, fb + 2048);

    // scores = cfeat_n @ memK^T / sqrt(512)
    gemm_kernel<true, false, 2, 1><<<dim3(32, 8, 1), 256>>>(
        512, sbuf + 256, 1280, memK, 512, nullptr, sc, 4096, 0.04419417382f);
    softmax_kernel<<<1024, 256>>>(sc, 4096);

    // m_out = attn @ memV  (split-K=4, atomic into g_s[:,768:1280])
    gemm_kernel<false, false, 0, 4><<<dim3(4, 8, 4), 256>>>(
        4096, sc, 4096, memV, 512, nullptr, sbuf + 768, 1280, 0.f);

    // s -> fp16 plane, then tensor-core FC (1 MMA per fragment)
    splitA_kernel<<<5120, 256>>>(sbuf, gAh);
    cudaFuncSetAttribute(fc_mma_kernel, cudaFuncAttributeMaxDynamicSharedMemorySize, 40960);
    fc_mma_kernel<<<dim3(8, 250), 256, 40960>>>(gAh, gBh, fcb, out);

    softmax_kernel<<<1024, 256>>>(out, 32000);
}

// round 10
// speedup vs baseline: 1.2031x; 1.0197x over previous
#include <cuda_runtime.h>
#include <cuda_bf16.h>
#include <cuda_fp16.h>
#include <cstdint>

#define DEV __device__ __forceinline__

// B=32,S=32 -> N=1024 ; CTX=64 ; E=256 ; V=32000 ; D=512 ; MEM=4096
// L1: Cin=64 Lin=256 -> 32x127 | L2: 32x127 -> 64x62 | L3: 64x62 -> 128x30
// L4: 128x30 -> 256x14 (HALF lane packing) | L5: GEMM [1024,3584]x[512,3584]^T
// FC: [1024,1280] x [1280,32000] via mma.sync fp16 (1 MMA/frag, err ~1.9e-4)
// Convs 2-4: CO_T=8 (8-channel register blocking -> half the LDS traffic)

__device__ float g_h1[1024 * 32 * 127];
__device__ float g_h2[1024 * 64 * 62];
__device__ float g_h3[1024 * 128 * 30];
__device__ float g_h4[1024 * 256 * 14];
__device__ float g_h4n[1024 * 3584];
__device__ float g_cfeat[1024 * 512];
__device__ float g_s[1024 * 1280];        // [ e(256) | cfeat_n(512) | m_out(512) ]
__device__ float g_scores[1024 * 4096];
__device__ float g_sum[5 * 512];
__device__ float g_ssq[5 * 512];
__device__ float g_affa[5 * 512];
__device__ float g_affb[5 * 512];
__device__ __half g_Bh[32000 * 1280];
__device__ __half g_Ah[1024 * 1280];

DEV float leakyf(float v) { return v > 0.f ? v : 0.1f * v; }

// fast exp on the fma pipe: exp(x) = 2^(x*log2e), magic-round + deg-5 poly
DEV float fast_exp(float x) {
    x = fmaxf(x, -80.f);
    float t = x * 1.4426950408889634f;
    float fm = t + 12582912.f;
    int ki = __float_as_int(fm);
    float f = t - (fm - 12582912.f);
    float p = 1.3333558146e-3f;
    p = fmaf(p, f, 9.6181291076e-3f);
    p = fmaf(p, f, 5.5504108664e-2f);
    p = fmaf(p, f, 2.4022650695e-1f);
    p = fmaf(p, f, 6.9314718056e-1f);
    p = fmaf(p, f, 1.0f);
    return p * __int_as_float((ki + (127 - 0x4B400000)) << 23);
}

__global__ void init_kernel() {
    int i = blockIdx.x * 256 + threadIdx.x;
    if (i < 5 * 512) { g_sum[i] = 0.f; g_ssq[i] = 0.f; }
    if (i < 1024 * 512) g_cfeat[i] = 0.f;
}

// ---------------- conv + leaky + stats -----------------------------
// HALF: lanes 0-15 handle channels [co0, co0+CO_T), lanes 16-31 handle
// [co0+CO_T, co0+2*CO_T) at the same output positions.
template <int CIN, int LIN, int COUT, int LOUT, int G, int CO_T, bool GATHER, bool HALF>
__global__ void __launch_bounds__(256) conv_kernel(
    const float* __restrict__ in, const int* __restrict__ cidx,
    const float* __restrict__ emb,
    const float* __restrict__ w, const float* __restrict__ bias,
    const float* __restrict__ aa, const float* __restrict__ ab,
    float* __restrict__ out, float* __restrict__ ssum, float* __restrict__ ssq)
{
    constexpr int KS = 8, PAD = 2;
    constexpr int SW = ((LIN + 2 * PAD + 1) / 2) * 2;
    extern __shared__ __align__(16) float in_s[];       // [CIN][SW]

    const int n = blockIdx.x;
    const int tid = threadIdx.x, warp = tid >> 5, lane = tid & 31;
    const int lpos = HALF ? (lane & 15) : lane;
    const int lhalf = HALF ? (lane >> 4) : 0;

    for (int i = tid; i < CIN * SW; i += 256) in_s[i] = 0.f;
    __syncthreads();

    if (GATHER) {
        for (int r = warp; r < CIN; r += 8) {
            int tok = cidx[n * CIN + r];
            const float4* src = (const float4*)(emb + (size_t)tok * 256);
            float* dst = &in_s[r * SW + PAD];
            #pragma unroll
            for (int i = 0; i < 2; i++) {
                float4 v = src[lane + 32 * i];
                int cb = (lane + 32 * i) * 4;
                dst[cb] = v.x; dst[cb + 1] = v.y; dst[cb + 2] = v.z; dst[cb + 3] = v.w;
            }
        }
    } else {
        for (int j = tid; j < CIN * LIN; j += 256) {
            int cin = j / LIN, l = j - cin * LIN;
            in_s[cin * SW + PAD + l] = aa[cin] * in[(size_t)n * CIN * LIN + j] + ab[cin];
        }
    }
    __syncthreads();

    int lo[G]; bool act[G];
    #pragma unroll
    for (int g = 0; g < G; g++) {
        int l = lpos + 32 * g;
        act[g] = (l < LOUT);
        lo[g] = act[g] ? l : (LOUT - 1);
    }

    constexpr int CPW = HALF ? (2 * CO_T) : CO_T;
    constexpr int OI = COUT / (8 * CPW);
    #pragma unroll 1
    for (int oi = 0; oi < OI; oi++) {
        const int co0 = (oi * 8 + warp) * CPW + lhalf * CO_T;
        float acc[CO_T][G];
        #pragma unroll
        for (int ct = 0; ct < CO_T; ct++) {
            float bv = bias[co0 + ct];
            #pragma unroll
            for (int g = 0; g < G; g++) acc[ct][g] = bv;
        }
        for (int cin = 0; cin < CIN; cin++) {
            const float* row = &in_s[cin * SW];
            float inv[G][KS];
            #pragma unroll
            for (int g = 0; g < G; g++) {
                int base = lo[g] * 2;
                #pragma unroll
                for (int kk = 0; kk < KS / 2; kk++) {
                    float2 p = *(const float2*)&row[base + 2 * kk];
                    inv[g][2 * kk] = p.x; inv[g][2 * kk + 1] = p.y;
                }
            }
            #pragma unroll
            for (int ct = 0; ct < CO_T; ct++) {
                const float4* wp = (const float4*)&w[((size_t)(co0 + ct) * CIN + cin) * KS];
                float4 w0 = __ldg(wp), w1 = __ldg(wp + 1);
                #pragma unroll
                for (int g = 0; g < G; g++) {
                    float a = acc[ct][g];
                    a = fmaf(w0.x, inv[g][0], a); a = fmaf(w0.y, inv[g][1], a);
                    a = fmaf(w0.z, inv[g][2], a); a = fmaf(w0.w, inv[g][3], a);
                    a = fmaf(w1.x, inv[g][4], a); a = fmaf(w1.y, inv[g][5], a);
                    a = fmaf(w1.z, inv[g][6], a); a = fmaf(w1.w, inv[g][7], a);
                    acc[ct][g] = a;
                }
            }
        }
        #pragma unroll
        for (int ct = 0; ct < CO_T; ct++) {
            const int co = co0 + ct;
            float s = 0.f, s2 = 0.f;
            #pragma unroll
            for (int g = 0; g < G; g++) {
                if (act[g]) {
                    float y = leakyf(acc[ct][g]);
                    out[((size_t)n * COUT + co) * LOUT + lo[g]] = y;
                    s += y; s2 += y * y;
                }
            }
            #pragma unroll
            for (int o = (HALF ? 8 : 16); o; o >>= 1) {
                s  += __shfl_xor_sync(~0u, s,  o);
                s2 += __shfl_xor_sync(~0u, s2, o);
            }
            if (lpos == 0) { atomicAdd(&ssum[co], s); atomicAdd(&ssq[co], s2); }
        }
    }
}

__global__ void bn_finalize_kernel(const float* __restrict__ ssum, const float* __restrict__ ssq,
                                   const float* __restrict__ gam, const float* __restrict__ bet,
                                   float* __restrict__ a, float* __restrict__ b,
                                   int cout, float invcnt)
{
    int c = threadIdx.x;
    if (c < cout) {
        float mu = ssum[c] * invcnt;
        float var = ssq[c] * invcnt - mu * mu;
        float av = gam[c] * rsqrtf(var + 1e-5f);
        a[c] = av;
        b[c] = bet[c] - mu * av;
    }
}

__global__ void affine4_kernel(const float* __restrict__ a, const float* __restrict__ b) {
    unsigned i = blockIdx.x * 256 + threadIdx.x;
    if (i < 1024u * 3584u) {
        unsigned cin = (i / 14u) & 255u;
        g_h4n[i] = a[cin] * g_h4[i] + b[cin];
    }
}

__global__ void colstats_kernel(const float* __restrict__ b5,
                                float* __restrict__ ssum, float* __restrict__ ssq) {
    int c = threadIdx.x;                  // 512 threads, 8 blocks x 128 rows
    int r0 = blockIdx.x * 128;
    float s = 0.f, s2 = 0.f;
    for (int r = 0; r < 128; r++) {
        float v = leakyf(g_cfeat[(size_t)(r0 + r) * 512 + c] + b5[c]);
        s += v; s2 += v * v;
    }
    atomicAdd(&ssum[c], s); atomicAdd(&ssq[c], s2);
}

__global__ void build_s_kernel(const int* __restrict__ x, const float* __restrict__ emb,
                               const float* __restrict__ b5,
                               const float* __restrict__ a5, const float* __restrict__ bb5) {
    int n = blockIdx.x, t = threadIdx.x;
    int tok = x[n];
    g_s[(size_t)n * 1280 + t] = emb[(size_t)tok * 256 + t];
    for (int j = t; j < 512; j += 256) {
        float y = leakyf(g_cfeat[(size_t)n * 512 + j] + b5[j]);
        g_s[(size_t)n * 1280 + 256 + j] = a5[j] * y + bb5[j];
        g_s[(size_t)n * 1280 + 768 + j] = 0.f;
    }
}

// ---------------- FFMA2 helpers (SIMT GEMM) -------------------------
DEV unsigned long long pk2(float x, float y) {
    unsigned long long r;
    asm("mov.b64 %0, {%1, %2};" : "=l"(r) : "r"(__float_as_uint(x)), "r"(__float_as_uint(y)));
    return r;
}
DEV void fma2(unsigned long long& d, unsigned long long a, unsigned long long b) {
    asm("fma.rn.f32x2 %0, %1, %2, %0;" : "+l"(d) : "l"(a), "l"(b));
}
DEV float2 unpk(unsigned long long v) {
    return make_float2(__uint_as_float((unsigned)v), __uint_as_float((unsigned)(v >> 32)));
}

// ---------------- 128x128x8 fp32 SIMT GEMM --------------------------
template <bool TB, bool BIAS, int EPI, int SPLIT>
__global__ void __launch_bounds__(256) gemm_kernel(
    int K, const float* __restrict__ A, int lda,
    const float* __restrict__ B, int ldb,
    const float* __restrict__ bias,
    float* __restrict__ C, int ldc, float scale)
{
    __shared__ __align__(16) float As[8][128];
    __shared__ __align__(16) float Bs[8][128];
    const int tid = threadIdx.x;
    const int tx = tid & 15, ty = tid >> 4;
    const int bn = blockIdx.x, bm = blockIdx.y;

    const int kb = K / SPLIT;
    const int k0 = blockIdx.z * kb;

    const int aRow = tid >> 1, aCol = (tid & 1) * 4;
    const int bRow = tid >> 5, bCol = (tid & 31) * 4;

    const float* Ap = A + (size_t)(bm * 128 + aRow) * lda + k0 + aCol;
    const float* Bp = TB ? (B + (size_t)(bn * 128 + aRow) * ldb + k0 + aCol)
                         : (B + (size_t)(k0 + bRow) * ldb + bn * 128 + bCol);

    unsigned long long acc[8][4];
    #pragma unroll
    for (int i = 0; i < 8; i++)
        #pragma unroll
        for (int j = 0; j < 4; j++) acc[i][j] = 0ull;

    const int T = kb / 8;
    float4 av = *(const float4*)Ap;
    float4 bv = *(const float4*)Bp;

    for (int kt = 0; kt < T; kt++) {
        As[aCol + 0][aRow] = av.x; As[aCol + 1][aRow] = av.y;
        As[aCol + 2][aRow] = av.z; As[aCol + 3][aRow] = av.w;
        if (TB) {
            Bs[aCol + 0][aRow] = bv.x; Bs[aCol + 1][aRow] = bv.y;
            Bs[aCol + 2][aRow] = bv.z; Bs[aCol + 3][aRow] = bv.w;
        } else {
            *(float4*)&Bs[bRow][bCol] = bv;
        }
        __syncthreads();
        if (kt + 1 < T) {
            av = *(const float4*)(Ap + (size_t)(kt + 1) * 8);
            bv = TB ? *(const float4*)(Bp + (size_t)(kt + 1) * 8)
                    : *(const float4*)(Bp + (size_t)(kt + 1) * 8 * ldb);
        }
        #pragma unroll
        for (int k = 0; k < 8; k++) {
            const float4 a0 = *(const float4*)&As[k][ty * 8];
            const float4 a1 = *(const float4*)&As[k][ty * 8 + 4];
            const float4 b0 = *(const float4*)&Bs[k][tx * 8];
            const float4 b1 = *(const float4*)&Bs[k][tx * 8 + 4];
            unsigned long long bp[4] = { pk2(b0.x, b0.y), pk2(b0.z, b0.w),
                                         pk2(b1.x, b1.y), pk2(b1.z, b1.w) };
            float am[8] = { a0.x, a0.y, a0.z, a0.w, a1.x, a1.y, a1.z, a1.w };
            #pragma unroll
            for (int i = 0; i < 8; i++) {
                unsigned long long ap = pk2(am[i], am[i]);
                #pragma unroll
                for (int j = 0; j < 4; j++) fma2(acc[i][j], ap, bp[j]);
            }
        }
        __syncthreads();
    }

    const int row0 = bm * 128 + ty * 8;
    const int col0 = bn * 128 + tx * 8;
    float bvals[8];
    if (BIAS) {
        #pragma unroll
        for (int j = 0; j < 8; j++) bvals[j] = bias[col0 + j];
    }
    #pragma unroll
    for (int i = 0; i < 8; i++) {
        float f[8];
        #pragma unroll
        for (int j = 0; j < 4; j++) {
            float2 u = unpk(acc[i][j]);
            f[2 * j] = u.x; f[2 * j + 1] = u.y;
        }
        if (SPLIT > 1) {
            #pragma unroll
            for (int j = 0; j < 8; j++)
                atomicAdd(&C[(size_t)(row0 + i) * ldc + col0 + j], f[j]);
        } else {
            #pragma unroll
            for (int j = 0; j < 8; j++) {
                if (BIAS) f[j] += bvals[j];
                if (EPI == 1) f[j] = leakyf(f[j]);
                if (EPI == 2) f[j] *= scale;
            }
            float* cp = &C[(size_t)(row0 + i) * ldc + col0];
            *(float4*)cp = make_float4(f[0], f[1], f[2], f[3]);
            *(float4*)(cp + 4) = make_float4(f[4], f[5], f[6], f[7]);
        }
    }
}

// ---------------- row softmax (poly exp on fma pipe) ----------------
__global__ void __launch_bounds__(256) softmax_kernel(float* __restrict__ buf, int W) {
    float* row = buf + (size_t)blockIdx.x * W;
    __shared__ float red[8];
    const int t = threadIdx.x, lane = t & 31, wp = t >> 5;

    float m = -3.402823e38f;
    for (int i = t; i < W; i += 256) m = fmaxf(m, row[i]);
    #pragma unroll
    for (int o = 16; o; o >>= 1) m = fmaxf(m, __shfl_xor_sync(~0u, m, o));
    if (lane == 0) red[wp] = m;
    __syncthreads();
    float mm = red[0];
    #pragma unroll
    for (int i = 1; i < 8; i++) mm = fmaxf(mm, red[i]);
    __syncthreads();

    float s = 0.f;
    for (int i = t; i < W; i += 256) { float e = fast_exp(row[i] - mm); row[i] = e; s += e; }
    #pragma unroll
    for (int o = 16; o; o >>= 1) s += __shfl_xor_sync(~0u, s, o);
    if (lane == 0) red[wp] = s;
    __syncthreads();
    float tot = red[0];
    #pragma unroll
    for (int i = 1; i < 8; i++) tot += red[i];
    float inv = 1.f / tot;
    for (int i = t; i < W; i += 256) row[i] *= inv;
}

// ======================= tensor-core FC path ========================

// transpose fcW [1280][32000] -> single fp16 plane [32000][1280]
__global__ void transW_kernel(const float* __restrict__ W, __half* __restrict__ Bh) {
    __shared__ float t[32][33];
    int n0 = blockIdx.x * 32, k0 = blockIdx.y * 32;
    for (int i = threadIdx.y; i < 32; i += 8)
        t[i][threadIdx.x] = W[(size_t)(k0 + i) * 32000 + n0 + threadIdx.x];
    __syncthreads();
    for (int i = threadIdx.y; i < 32; i += 8) {
        float v = t[threadIdx.x][i];
        Bh[(size_t)(n0 + i) * 1280 + k0 + threadIdx.x] = __float2half(v);
    }
}

// s -> single fp16 plane
__global__ void splitA_kernel(const float* __restrict__ S, __half* __restrict__ Ah) {
    int i = blockIdx.x * 256 + threadIdx.x;   // grid covers 1024*1280
    Ah[i] = __float2half(S[i]);
}

DEV uint32_t smem_u32(const void* p) {
    uint32_t a;
    asm("{ .reg .u64 t; cvta.to.shared.u64 t, %1; cvt.u32.u64 %0, t; }" : "=r"(a) : "l"(p));
    return a;
}

DEV void ldsm4(uint32_t* r, uint32_t addr) {
    asm volatile("ldmatrix.sync.aligned.m8n8.x4.shared.b16 {%0,%1,%2,%3}, [%4];"
                 : "=r"(r[0]), "=r"(r[1]), "=r"(r[2]), "=r"(r[3]) : "r"(addr));
}
DEV void ldsm2(uint32_t* r, uint32_t addr) {
    asm volatile("ldmatrix.sync.aligned.m8n8.x2.shared.b16 {%0,%1}, [%2];"
                 : "=r"(r[0]), "=r"(r[1]) : "r"(addr));
}
DEV void mma16816f(float* d, const uint32_t* a, const uint32_t* b) {
    asm volatile(
        "mma.sync.aligned.m16n8k16.row.col.f32.f16.f16.f32 "
        "{%0,%1,%2,%3}, {%4,%5,%6,%7}, {%8,%9}, {%0,%1,%2,%3};"
        : "+f"(d[0]), "+f"(d[1]), "+f"(d[2]), "+f"(d[3])
        : "r"(a[0]), "r"(a[1]), "r"(a[2]), "r"(a[3]), "r"(b[0]), "r"(b[1]));
}

// C[1024,32000] = Ah @ Bh^T + bias ; 128x128 tiles, 8 warps (2M x 4N),
// warp tile 64x32, BK=32, cp.async double buffer, smem row stride 80B.
__global__ void __launch_bounds__(256) fc_mma_kernel(
    const __half* __restrict__ Ah, const __half* __restrict__ Bh,
    const float* __restrict__ bias, float* __restrict__ C)
{
    extern __shared__ __align__(16) char smem[];
    const int tid = threadIdx.x, lane = tid & 31, warp = tid >> 5;
    const int wm = warp & 1, wn = warp >> 1;
    const int row0 = blockIdx.x * 128, col0 = blockIdx.y * 128;

    const uint32_t sb = smem_u32(smem);
    constexpr uint32_t PLANE = 10240;        // 128 rows * 80 B
    constexpr uint32_t STAGE = 2 * PLANE;    // Ah | Bh

    const __half* src0 = Ah + (size_t)row0 * 1280;
    const __half* src1 = Bh + (size_t)col0 * 1280;

    const int lrow = tid >> 2, lseg = tid & 3;

    auto load_stage = [&](int chunk, int buf) {
        const uint32_t dst0 = sb + (uint32_t)buf * STAGE;
        const int k0 = chunk * 32;
        const __half* srcs[2] = { src0, src1 };
        #pragma unroll
        for (int p = 0; p < 2; p++) {
            #pragma unroll
            for (int i = 0; i < 2; i++) {
                int row = lrow + 64 * i;
                uint32_t d = dst0 + (uint32_t)p * PLANE + row * 80 + lseg * 16;
                const void* s = srcs[p] + (size_t)row * 1280 + k0 + lseg * 8;
                asm volatile("cp.async.cg.shared.global [%0], [%1], 16;"
                             :: "r"(d), "l"(s) : "memory");
            }
        }
        asm volatile("cp.async.commit_group;" ::: "memory");
    };

    float acc[4][4][4];
    #pragma unroll
    for (int mi = 0; mi < 4; mi++)
        #pragma unroll
        for (int ni = 0; ni < 4; ni++)
            #pragma unroll
            for (int j = 0; j < 4; j++) acc[mi][ni][j] = 0.f;

    load_stage(0, 0);

    constexpr int CH = 40;                   // 1280 / 32
    for (int c = 0; c < CH; c++) {
        if (c + 1 < CH) {
            load_stage(c + 1, (c + 1) & 1);
            asm volatile("cp.async.wait_group 1;" ::: "memory");
        } else {
            asm volatile("cp.async.wait_group 0;" ::: "memory");
        }
        __syncthreads();

        const uint32_t st = sb + (uint32_t)(c & 1) * STAGE;
        #pragma unroll
        for (int ks = 0; ks < 2; ks++) {
            uint32_t ah[4][4], bh[4][2];
            #pragma unroll
            for (int mi = 0; mi < 4; mi++) {
                int row = wm * 64 + mi * 16 + (lane & 15);
                uint32_t off = (uint32_t)row * 80 + ks * 32 + (lane >> 4) * 16;
                ldsm4(ah[mi], st + off);
            }
            #pragma unroll
            for (int ni = 0; ni < 4; ni++) {
                int row = wn * 32 + ni * 8 + (lane & 7);
                uint32_t off = (uint32_t)row * 80 + ks * 32 + ((lane >> 3) & 1) * 16;
                ldsm2(bh[ni], st + PLANE + off);
            }
            #pragma unroll
            for (int mi = 0; mi < 4; mi++)
                #pragma unroll
                for (int ni = 0; ni < 4; ni++)
                    mma16816f(acc[mi][ni], ah[mi], bh[ni]);
        }
        __syncthreads();
    }

    #pragma unroll
    for (int mi = 0; mi < 4; mi++) {
        int r = row0 + wm * 64 + mi * 16 + (lane >> 2);
        #pragma unroll
        for (int ni = 0; ni < 4; ni++) {
            int cc = col0 + wn * 32 + ni * 8 + (lane & 3) * 2;
            float b0 = bias[cc], b1 = bias[cc + 1];
            float* p0 = C + (size_t)r * 32000 + cc;
            float* p1 = p0 + (size_t)8 * 32000;
            *(float2*)p0 = make_float2(acc[mi][ni][0] + b0, acc[mi][ni][1] + b1);
            *(float2*)p1 = make_float2(acc[mi][ni][2] + b0, acc[mi][ni][3] + b1);
        }
    }
}

// ------------------------------------------------------------------
extern "C" void kernel_launch(void* const* d_in, const int* in_sizes, int n_in,
                              void* d_out, int out_size)
{
    (void)in_sizes; (void)n_in; (void)out_size;
    const int*   x    = (const int*)  d_in[0];
    const int*   c    = (const int*)  d_in[1];
    const float* emb  = (const float*)d_in[2];
    const float* w1 = (const float*)d_in[3],  *b1 = (const float*)d_in[4];
    const float* gm1= (const float*)d_in[5],  *be1= (const float*)d_in[6];
    const float* w2 = (const float*)d_in[7],  *b2 = (const float*)d_in[8];
    const float* gm2= (const float*)d_in[9],  *be2= (const float*)d_in[10];
    const float* w3 = (const float*)d_in[11], *b3 = (const float*)d_in[12];
    const float* gm3= (const float*)d_in[13], *be3= (const float*)d_in[14];
    const float* w4 = (const float*)d_in[15], *b4 = (const float*)d_in[16];
    const float* gm4= (const float*)d_in[17], *be4= (const float*)d_in[18];
    const float* w5 = (const float*)d_in[19], *b5 = (const float*)d_in[20];
    const float* gm5= (const float*)d_in[21], *be5= (const float*)d_in[22];
    const float* fcW = (const float*)d_in[23], *fcb = (const float*)d_in[24];
    const float* memK= (const float*)d_in[25], *memV= (const float*)d_in[26];
    float* out = (float*)d_out;

    float *h1, *h2, *h3, *h4, *h4n, *cf, *sbuf, *sc, *su, *sq, *fa, *fb;
    __half *gBh, *gAh;
    cudaGetSymbolAddress((void**)&h1, g_h1);
    cudaGetSymbolAddress((void**)&h2, g_h2);
    cudaGetSymbolAddress((void**)&h3, g_h3);
    cudaGetSymbolAddress((void**)&h4, g_h4);
    cudaGetSymbolAddress((void**)&h4n, g_h4n);
    cudaGetSymbolAddress((void**)&cf, g_cfeat);
    cudaGetSymbolAddress((void**)&sbuf, g_s);
    cudaGetSymbolAddress((void**)&sc, g_scores);
    cudaGetSymbolAddress((void**)&su, g_sum);
    cudaGetSymbolAddress((void**)&sq, g_ssq);
    cudaGetSymbolAddress((void**)&fa, g_affa);
    cudaGetSymbolAddress((void**)&fb, g_affb);
    cudaGetSymbolAddress((void**)&gBh, g_Bh);
    cudaGetSymbolAddress((void**)&gAh, g_Ah);

    init_kernel<<<2048, 256>>>();

    // fcW -> single fp16 plane (depends only on fcW)
    transW_kernel<<<dim3(1000, 40), dim3(32, 8)>>>(fcW, gBh);

    // conv1: gather emb, CIN=64 LIN=256 -> 32x127. smem 66560 B
    auto k1 = conv_kernel<64, 256, 32, 127, 4, 4, true, false>;
    cudaFuncSetAttribute(k1, cudaFuncAttributeMaxDynamicSharedMemorySize, 66560);
    k1<<<1024, 256, 66560>>>(nullptr, c, emb, w1, b1, nullptr, nullptr,
                             h1, su + 0, sq + 0);
    bn_finalize_kernel<<<1, 512>>>(su + 0, sq + 0, gm1, be1, fa + 0, fb + 0,
                                   32, 1.f / (1024.f * 127.f));

    // conv2: CO_T=8 (single OI pass, half the LDS traffic)
    conv_kernel<32, 127, 64, 62, 2, 8, false, false><<<1024, 256, 32 * 132 * 4>>>(
        h1, nullptr, nullptr, w2, b2, fa + 0, fb + 0, h2, su + 512, sq + 512);
    bn_finalize_kernel<<<1, 512>>>(su + 512, sq + 512, gm2, be2, fa + 512, fb + 512,
                                   64, 1.f / (1024.f * 62.f));

    // conv3: CO_T=8
    conv_kernel<64, 62, 128, 30, 1, 8, false, false><<<1024, 256, 64 * 66 * 4>>>(
        h2, nullptr, nullptr, w3, b3, fa + 512, fb + 512, h3, su + 1024, sq + 1024);
    bn_finalize_kernel<<<1, 512>>>(su + 1024, sq + 1024, gm3, be3, fa + 1024, fb + 1024,
                                   128, 1.f / (1024.f * 30.f));

    // conv4: HALF lane packing + CO_T=8
    conv_kernel<128, 30, 256, 14, 1, 8, false, true><<<1024, 256, 128 * 34 * 4>>>(
        h3, nullptr, nullptr, w4, b4, fa + 1024, fb + 1024, h4, su + 1536, sq + 1536);
    bn_finalize_kernel<<<1, 512>>>(su + 1536, sq + 1536, gm4, be4, fa + 1536, fb + 1536,
                                   256, 1.f / (1024.f * 14.f));

    affine4_kernel<<<14336, 256>>>(fa + 1536, fb + 1536);

    // conv5 as GEMM: [1024,3584] x [512,3584]^T -> g_cfeat (split-K=4, atomic)
    gemm_kernel<true, false, 0, 4><<<dim3(4, 8, 4), 256>>>(
        3584, h4n, 3584, w5, 3584, nullptr, cf, 512, 0.f);

    colstats_kernel<<<8, 512>>>(b5, su + 2048, sq + 2048);
    bn_finalize_kernel<<<1, 512>>>(su + 2048, sq + 2048, gm5, be5, fa + 2048, fb + 2048,
                                   512, 1.f / 1024.f);
    build_s_kernel<<<1024, 256>>>(x, emb, b5, fa + 2048, fb + 2048);

    // scores = cfeat_n @ memK^T / sqrt(512)
    gemm_kernel<true, false, 2, 1><<<dim3(32, 8, 1), 256>>>(
        512, sbuf + 256, 1280, memK, 512, nullptr, sc, 4096, 0.04419417382f);
    softmax_kernel<<<1024, 256>>>(sc, 4096);

    // m_out = attn @ memV  (split-K=4, atomic into g_s[:,768:1280])
    gemm_kernel<false, false, 0, 4><<<dim3(4, 8, 4), 256>>>(
        4096, sc, 4096, memV, 512, nullptr, sbuf + 768, 1280, 0.f);

    // s -> fp16 plane, then tensor-core FC (1 MMA per fragment)
    splitA_kernel<<<5120, 256>>>(sbuf, gAh);
    cudaFuncSetAttribute(fc_mma_kernel, cudaFuncAttributeMaxDynamicSharedMemorySize, 40960);
    fc_mma_kernel<<<dim3(8, 250), 256, 40960>>>(gAh, gBh, fcb, out);

    softmax_kernel<<<1024, 256>>>(out, 32000);
}